// round 14
// baseline (speedup 1.0000x reference)
#include <cuda_runtime.h>
#include <cuda_fp16.h>
#include <cstdint>
#include <cstddef>

#define B_    8
#define T_    8192
#define D_    512
#define H_    4
#define P_    24
#define HD_   128
#define TOPK_ 12
#define NC_   16
#define CHUNK_ 512
#define PSTR  514   // per-proto partial stride: m, l, U[512]

// ---------------- scratch (static device globals; no allocation) ----------------
__device__ __align__(16) __half g_xh[(size_t)B_ * T_ * D_];   // xn (fp16)
__device__ __align__(16) __half g_Wh[2 * D_ * D_];            // Wk, Wv (fp16)
__device__ __align__(16) __half g_K [(size_t)B_ * T_ * D_];   // K (fp16)
__device__ float g_Qh[H_ * P_ * HD_];
__device__ float g_part[(size_t)B_ * H_ * NC_ * P_ * PSTR];
__device__ float g_pt[B_ * P_ * D_];

// ---------------- helpers ----------------
__device__ __forceinline__ uint32_t smem_u32(const void* p) {
    uint32_t a;
    asm("{ .reg .u64 t; cvta.to.shared.u64 t, %1; cvt.u32.u64 %0, t; }" : "=r"(a) : "l"(p));
    return a;
}
__device__ __forceinline__ void cp16(uint32_t s, const void* g) {
    asm volatile("cp.async.cg.shared.global [%0], [%1], 16;" :: "r"(s), "l"(g) : "memory");
}
__device__ __forceinline__ void cp_commit() {
    asm volatile("cp.async.commit_group;" ::: "memory");
}
template <int N> __device__ __forceinline__ void cp_wait() {
    asm volatile("cp.async.wait_group %0;" :: "n"(N) : "memory");
}
__device__ __forceinline__ void ldsm4(uint32_t& r0, uint32_t& r1, uint32_t& r2, uint32_t& r3,
                                      uint32_t addr) {
    asm volatile("ldmatrix.sync.aligned.m8n8.x4.shared.b16 {%0,%1,%2,%3}, [%4];"
                 : "=r"(r0), "=r"(r1), "=r"(r2), "=r"(r3) : "r"(addr));
}
__device__ __forceinline__ void ldsm4t(uint32_t& r0, uint32_t& r1, uint32_t& r2, uint32_t& r3,
                                       uint32_t addr) {
    asm volatile("ldmatrix.sync.aligned.m8n8.x4.trans.shared.b16 {%0,%1,%2,%3}, [%4];"
                 : "=r"(r0), "=r"(r1), "=r"(r2), "=r"(r3) : "r"(addr));
}
__device__ __forceinline__ void mma_f16(float* c,
                                        uint32_t a0, uint32_t a1, uint32_t a2, uint32_t a3,
                                        uint32_t b0, uint32_t b1) {
    asm volatile("mma.sync.aligned.m16n8k16.row.col.f32.f16.f16.f32 "
                 "{%0,%1,%2,%3}, {%4,%5,%6,%7}, {%8,%9}, {%0,%1,%2,%3};"
                 : "+f"(c[0]), "+f"(c[1]), "+f"(c[2]), "+f"(c[3])
                 : "r"(a0), "r"(a1), "r"(a2), "r"(a3), "r"(b0), "r"(b1));
}
__device__ __forceinline__ void h8_unpack(uint4 r, float* o, float& nn) {
    float2 f;
    f = __half22float2(*(__half2*)&r.x); o[0] = f.x; o[1] = f.y; nn += f.x * f.x + f.y * f.y;
    f = __half22float2(*(__half2*)&r.y); o[2] = f.x; o[3] = f.y; nn += f.x * f.x + f.y * f.y;
    f = __half22float2(*(__half2*)&r.z); o[4] = f.x; o[5] = f.y; nn += f.x * f.x + f.y * f.y;
    f = __half22float2(*(__half2*)&r.w); o[6] = f.x; o[7] = f.y; nn += f.x * f.x + f.y * f.y;
}

// ---------------- 1. LayerNorm -> fp16 ----------------
__global__ __launch_bounds__(256) void ln_kernel(const float* __restrict__ x,
                                                 const float* __restrict__ gw,
                                                 const float* __restrict__ bw) {
    int lane = threadIdx.x & 31;
    size_t row = (size_t)blockIdx.x * 8 + (threadIdx.x >> 5);
    const float* xr = x + row * D_;
    float4 v[4];
    float s = 0.f, sq = 0.f;
#pragma unroll
    for (int j = 0; j < 4; j++) {
        v[j] = *(const float4*)&xr[lane * 4 + j * 128];
        s  += v[j].x + v[j].y + v[j].z + v[j].w;
        sq += v[j].x * v[j].x + v[j].y * v[j].y + v[j].z * v[j].z + v[j].w * v[j].w;
    }
#pragma unroll
    for (int o = 16; o > 0; o >>= 1) {
        s  += __shfl_xor_sync(0xffffffffu, s,  o);
        sq += __shfl_xor_sync(0xffffffffu, sq, o);
    }
    float mu   = s * (1.f / 512.f);
    float var  = sq * (1.f / 512.f) - mu * mu;
    float rstd = rsqrtf(var + 1e-5f);
#pragma unroll
    for (int j = 0; j < 4; j++) {
        int c = lane * 4 + j * 128;
        float4 gv = *(const float4*)&gw[c];
        float4 bv = *(const float4*)&bw[c];
        __half h[4];
        h[0] = __float2half_rn((v[j].x - mu) * rstd * gv.x + bv.x);
        h[1] = __float2half_rn((v[j].y - mu) * rstd * gv.y + bv.y);
        h[2] = __float2half_rn((v[j].z - mu) * rstd * gv.z + bv.z);
        h[3] = __float2half_rn((v[j].w - mu) * rstd * gv.w + bv.w);
        *(uint2*)&g_xh[row * D_ + c] = *(uint2*)h;
    }
}

// ---------------- 1b. W matrices -> fp16 ----------------
__global__ __launch_bounds__(256) void round_w(const float* __restrict__ Wk,
                                               const float* __restrict__ Wv) {
    int i = blockIdx.x * 256 + threadIdx.x;
    g_Wh[i]           = __float2half_rn(Wk[i]);
    g_Wh[D_ * D_ + i] = __float2half_rn(Wv[i]);
}

// ---------------- 2. fp16 mma GEMM: K = xn @ Wk^T ----------------
#define ROWB 80
#define TILE_B (128 * ROWB)
#define STAGE_B (2 * TILE_B)
#define GEMM_SMEM (3 * STAGE_B)    // 61440 B

__global__ __launch_bounds__(256, 2) void gemm_f16() {
    extern __shared__ __align__(16) char smc[];
    const uint32_t sb = smem_u32(smc);

    const int tid = threadIdx.x;
    const int wid = tid >> 5, lane = tid & 31;
    const int n0 = blockIdx.x * 128;
    const size_t m0 = (size_t)blockIdx.y * 128;

    const __half* A_g = g_xh;
    const __half* B_g = g_Wh;           // Wk
    __half* C = g_K;

    const int lrow = tid >> 1;
    const int lch  = tid & 1;
    const size_t gA = (m0 + lrow) * D_ + lch * 16;
    const size_t gB = (size_t)(n0 + lrow) * D_ + lch * 16;
    const uint32_t sRow = (uint32_t)lrow * ROWB + lch * 32;

    const int wm = (wid >> 2) * 64;
    const int wn = (wid & 3) * 32;
    const int g  = lane >> 2;
    const int t  = lane & 3;

    uint32_t aRow[4], bRow[2];
#pragma unroll
    for (int mi = 0; mi < 4; mi++)
        aRow[mi] = (uint32_t)(wm + mi * 16 + (lane & 15)) * ROWB + ((lane & 16) ? 16 : 0);
#pragma unroll
    for (int np = 0; np < 2; np++)
        bRow[np] = (uint32_t)(wn + np * 16 + ((lane & 16) ? 8 : 0) + (lane & 7)) * ROWB
                   + ((lane & 8) ? 16 : 0);

    float c[4][4][4];
#pragma unroll
    for (int mi = 0; mi < 4; mi++)
#pragma unroll
        for (int ni = 0; ni < 4; ni++)
#pragma unroll
            for (int j = 0; j < 4; j++) c[mi][ni][j] = 0.f;

    auto stage = [&](int st, int kt) {
        uint32_t bbA = sb + (uint32_t)st * STAGE_B;
        uint32_t bbB = bbA + TILE_B;
        int ke = kt * 32;
        cp16(bbA + sRow,      A_g + gA + ke);
        cp16(bbA + sRow + 16, A_g + gA + ke + 8);
        cp16(bbB + sRow,      B_g + gB + ke);
        cp16(bbB + sRow + 16, B_g + gB + ke + 8);
        cp_commit();
    };

    stage(0, 0);
    stage(1, 1);

#pragma unroll 1
    for (int kt = 0; kt < 16; ++kt) {
        if (kt < 15) cp_wait<1>(); else cp_wait<0>();
        __syncthreads();
        if (kt + 2 < 16) stage((kt + 2) % 3, kt + 2);

        const uint32_t bbA = sb + (uint32_t)(kt % 3) * STAGE_B;
        const uint32_t bbB = bbA + TILE_B;

#pragma unroll
        for (int ks = 0; ks < 2; ks++) {
            const uint32_t ko = ks * 32;
            uint32_t a[4][4], bq[2][4];
#pragma unroll
            for (int mi = 0; mi < 4; mi++)
                ldsm4(a[mi][0], a[mi][1], a[mi][2], a[mi][3], bbA + aRow[mi] + ko);
#pragma unroll
            for (int np = 0; np < 2; np++)
                ldsm4(bq[np][0], bq[np][1], bq[np][2], bq[np][3], bbB + bRow[np] + ko);
#pragma unroll
            for (int mi = 0; mi < 4; mi++)
#pragma unroll
                for (int np = 0; np < 2; np++) {
                    mma_f16(c[mi][np * 2],     a[mi][0], a[mi][1], a[mi][2], a[mi][3],
                            bq[np][0], bq[np][1]);
                    mma_f16(c[mi][np * 2 + 1], a[mi][0], a[mi][1], a[mi][2], a[mi][3],
                            bq[np][2], bq[np][3]);
                }
        }
    }

#pragma unroll
    for (int mi = 0; mi < 4; mi++) {
#pragma unroll
        for (int ni = 0; ni < 4; ni++) {
            size_t r0 = m0 + wm + mi * 16 + g;
            int col = n0 + wn + ni * 8 + t * 2;
            *(__half2*)&C[r0 * D_ + col]       = __floats2half2_rn(c[mi][ni][0], c[mi][ni][1]);
            *(__half2*)&C[(r0 + 8) * D_ + col] = __floats2half2_rn(c[mi][ni][2], c[mi][ni][3]);
        }
    }
}

// ---------------- 3. Qh: grid (P, H), 512 threads ----------------
__global__ __launch_bounds__(512) void qh_kernel(const float* __restrict__ proto,
                                                 const float* __restrict__ Wq) {
    __shared__ float pr[D_];
    __shared__ float qp[HD_];
    __shared__ float sinv;
    int p = blockIdx.x, h = blockIdx.y, tid = threadIdx.x;
    pr[tid] = proto[p * D_ + tid];
    __syncthreads();
    int nl = tid >> 2, part = tid & 3;
    const float* wr = Wq + (size_t)(h * HD_ + nl) * D_ + part * 128;
    const float* pp = pr + part * 128;
    float a = 0.f;
#pragma unroll 8
    for (int k = 0; k < 128; k += 4) {
        float4 w4 = *(const float4*)&wr[k];
        a += w4.x * pp[k] + w4.y * pp[k + 1] + w4.z * pp[k + 2] + w4.w * pp[k + 3];
    }
    a += __shfl_xor_sync(0xffffffffu, a, 1);
    a += __shfl_xor_sync(0xffffffffu, a, 2);
    if (part == 0) qp[nl] = a;
    __syncthreads();
    if (tid < 32) {
        float sq = 0.f;
#pragma unroll
        for (int j = 0; j < 4; j++) { float tv = qp[tid + 32 * j]; sq += tv * tv; }
#pragma unroll
        for (int o = 16; o > 0; o >>= 1) sq += __shfl_xor_sync(0xffffffffu, sq, o);
        if (tid == 0) sinv = 1.f / fmaxf(sqrtf(sq), 1e-12f);
    }
    __syncthreads();
    if (tid < HD_) g_Qh[(h * P_ + p) * HD_ + tid] = qp[tid] * sinv;
}

// ---------------- 4. attention; ldmatrix fragments throughout ----------------
// grid (H, NC, B), 256 threads. smem 113920 B -> 2 CTAs/SM.
#define oQ   0
#define oKB  8704
#define KBUF 34816
#define oSP  78336
#define oNm  111616
#define oMs  113664
#define oLs  113792
#define ATT_SMEM 113920

__global__ __launch_bounds__(256, 2) void att_mma() {
    extern __shared__ __align__(16) char smc[];
    const uint32_t sb = smem_u32(smc);
    __half* Qs = (__half*)(smc + oQ);
    __half* SP = (__half*)(smc + oSP);     // scores then exp-weights, fp16, 32 x 520
    float*  Nm = (float*)(smc + oNm);
    float*  Ms = (float*)(smc + oMs);
    float*  Ls = (float*)(smc + oLs);

    const int tid = threadIdx.x;
    const int wid = tid >> 5, lane = tid & 31;
    const int g = lane >> 2, t = lane & 3;
    const int h = blockIdx.x, cz = blockIdx.y, b = blockIdx.z;
    const size_t tokbase = (size_t)(b * T_ + cz * CHUNK_);

    for (int i = tid; i < 32 * 128; i += 256) {
        int p = i >> 7, d = i & 127;
        float v = (p < P_) ? g_Qh[(h * P_ + p) * HD_ + d] : 0.f;
        Qs[p * 136 + d] = __float2half_rn(v);
    }

    // ldmatrix lane-address bases (bytes)
    uint32_t qA[2], pA[2];
#pragma unroll
    for (int mi = 0; mi < 2; mi++) {
        qA[mi] = sb + oQ  + (uint32_t)((mi * 16 + (lane & 15)) * 136 + ((lane & 16) ? 8 : 0)) * 2;
        pA[mi] = sb + oSP + (uint32_t)((mi * 16 + (lane & 15)) * 520 + ((lane & 16) ? 8 : 0)) * 2;
    }
    const uint32_t kB = (uint32_t)((wid * 16 + ((lane & 16) ? 8 : 0) + (lane & 7)) * 136
                                   + ((lane & 8) ? 8 : 0)) * 2;
    const uint32_t vT = (uint32_t)((lane & 15) * 136 + wid * 16 + ((lane & 16) ? 8 : 0)) * 2;

    auto stageK = [&](int st, int bf) {
        uint32_t bb = sb + oKB + (uint32_t)bf * KBUF;
#pragma unroll
        for (int j = 0; j < 8; j++) {
            int lin = tid + 256 * j;
            int tok = lin >> 4, ch = lin & 15;
            cp16(bb + (uint32_t)(tok * 136 + ch * 8) * 2,
                 g_K + (tokbase + st * 128 + tok) * D_ + h * HD_ + ch * 8);
        }
        cp_commit();
    };
    auto stageXN = [&](int dg, int st, int bf) {
        uint32_t bb = sb + oKB + (uint32_t)bf * KBUF;
#pragma unroll
        for (int j = 0; j < 8; j++) {
            int lin = tid + 256 * j;
            int tok = lin >> 4, ch = lin & 15;
            cp16(bb + (uint32_t)(tok * 136 + ch * 8) * 2,
                 g_xh + (tokbase + st * 128 + tok) * D_ + dg * 128 + ch * 8);
        }
        cp_commit();
    };

    stageK(0, 0);
    stageK(1, 1);

    // ================= scores (fp16 into SP) =================
#pragma unroll 1
    for (int st = 0; st < 4; ++st) {
        cp_wait<1>();
        __syncthreads();
        const uint32_t kbase = sb + oKB + (uint32_t)(st & 1) * KBUF;
        const __half* Kh = (const __half*)(smc + oKB + (st & 1) * KBUF);

        {
            int tok = tid >> 1, hf = tid & 1;
            const uint4* kp = (const uint4*)(Kh + tok * 136 + hf * 64);
            float nn = 0.f, tmp[8];
#pragma unroll
            for (int i = 0; i < 8; i++) h8_unpack(kp[i], tmp, nn);
            nn += __shfl_xor_sync(0xffffffffu, nn, 1);
            if (hf == 0) Nm[st * 128 + tok] = nn;
        }
        __syncthreads();

        float c[2][2][4] = {};
#pragma unroll
        for (int kt = 0; kt < 8; kt++) {
            uint32_t a[2][4], bq[4];
#pragma unroll
            for (int mi = 0; mi < 2; mi++)
                ldsm4(a[mi][0], a[mi][1], a[mi][2], a[mi][3], qA[mi] + kt * 32);
            ldsm4(bq[0], bq[1], bq[2], bq[3], kbase + kB + kt * 32);
#pragma unroll
            for (int mi = 0; mi < 2; mi++) {
                mma_f16(c[mi][0], a[mi][0], a[mi][1], a[mi][2], a[mi][3], bq[0], bq[1]);
                mma_f16(c[mi][1], a[mi][0], a[mi][1], a[mi][2], a[mi][3], bq[2], bq[3]);
            }
        }
#pragma unroll
        for (int np = 0; np < 2; np++) {
            int tc = wid * 16 + np * 8 + t * 2;
            float inv0 = 1.f / (fmaxf(sqrtf(Nm[st * 128 + tc]),     1e-12f) * 0.07f);
            float inv1 = 1.f / (fmaxf(sqrtf(Nm[st * 128 + tc + 1]), 1e-12f) * 0.07f);
#pragma unroll
            for (int mi = 0; mi < 2; mi++) {
                int r0 = mi * 16 + g;
                *(__half2*)&SP[r0 * 520 + st * 128 + tc] =
                    __floats2half2_rn(c[mi][np][0] * inv0, c[mi][np][1] * inv1);
                *(__half2*)&SP[(r0 + 8) * 520 + st * 128 + tc] =
                    __floats2half2_rn(c[mi][np][2] * inv0, c[mi][np][3] * inv1);
            }
        }
        __syncthreads();
        if (st < 2) stageK(st + 2, st & 1);
        else        stageXN(0, st - 2, st & 1);   // PV stages ls=0,1
    }

    // ================= softmax in place on SP =================
#pragma unroll 1
    for (int rr = 0; rr < 4; ++rr) {
        int p = wid + rr * 8;
        float vals[16];
        float m = -3.4e38f;
#pragma unroll
        for (int j = 0; j < 16; j++) {
            vals[j] = __half2float(SP[p * 520 + lane + 32 * j]);
            m = fmaxf(m, vals[j]);
        }
#pragma unroll
        for (int o = 16; o > 0; o >>= 1) m = fmaxf(m, __shfl_xor_sync(0xffffffffu, m, o));
        float s = 0.f;
#pragma unroll
        for (int j = 0; j < 16; j++) {
            float e = expf(vals[j] - m);
            SP[p * 520 + lane + 32 * j] = __float2half_rn(e);
            s += e;
        }
#pragma unroll
        for (int o = 16; o > 0; o >>= 1) s += __shfl_xor_sync(0xffffffffu, s, o);
        if (lane == 0) { Ms[p] = m; Ls[p] = s; }
    }

    // ================= PV: U = P @ xn =================
    size_t base = (((size_t)(b * H_ + h) * NC_ + cz) * P_) * PSTR;
    float cp2[2][2][4] = {};
#pragma unroll 1
    for (int ls = 0; ls < 16; ++ls) {
        int dg = ls >> 2, st = ls & 3;
        if (ls < 15) cp_wait<1>(); else cp_wait<0>();
        __syncthreads();
        uint32_t vb = sb + oKB + (uint32_t)(ls & 1) * KBUF;

#pragma unroll
        for (int kt = 0; kt < 8; kt++) {
            uint32_t a[2][4];
#pragma unroll
            for (int mi = 0; mi < 2; mi++)
                ldsm4(a[mi][0], a[mi][1], a[mi][2], a[mi][3],
                      pA[mi] + (st * 128 + kt * 16) * 2);
            uint32_t r0, r1, r2, r3;
            ldsm4t(r0, r1, r2, r3, vb + vT + (uint32_t)(kt * 16) * 272);
#pragma unroll
            for (int mi = 0; mi < 2; mi++) {
                mma_f16(cp2[mi][0], a[mi][0], a[mi][1], a[mi][2], a[mi][3], r0, r1);
                mma_f16(cp2[mi][1], a[mi][0], a[mi][1], a[mi][2], a[mi][3], r2, r3);
            }
        }
        __syncthreads();
        if (ls + 2 < 16) stageXN((ls + 2) >> 2, (ls + 2) & 3, ls & 1);

        if (st == 3) {
#pragma unroll
            for (int mi = 0; mi < 2; mi++)
#pragma unroll
                for (int np = 0; np < 2; np++)
#pragma unroll
                    for (int j = 0; j < 4; j++) {
                        int r = mi * 16 + g + ((j >> 1) ? 8 : 0);
                        if (r < P_) {
                            int col = dg * 128 + wid * 16 + np * 8 + t * 2 + (j & 1);
                            g_part[base + (size_t)r * PSTR + 2 + col] = cp2[mi][np][j];
                        }
                        cp2[mi][np][j] = 0.f;
                    }
        }
    }
    if (tid < P_) {
        g_part[base + (size_t)tid * PSTR]     = Ms[tid];
        g_part[base + (size_t)tid * PSTR + 1] = Ls[tid];
    }
}

// ---------------- 5. fused merge + Wv projection -> proto_tokens ----------------
__global__ __launch_bounds__(512) void mergeproj_kernel() {
    __shared__ float Us[D_];
    int p = blockIdx.x, h = blockIdx.y, b = blockIdx.z;
    int tid = threadIdx.x;
    {
        int d = tid;
        float M = -3.4e38f;
        for (int c = 0; c < NC_; c++) {
            const float* pp = g_part + (((size_t)(b * H_ + h) * NC_ + c) * P_ + p) * PSTR;
            M = fmaxf(M, pp[0]);
        }
        float L = 0.f, val = 0.f;
        for (int c = 0; c < NC_; c++) {
            const float* pp = g_part + (((size_t)(b * H_ + h) * NC_ + c) * P_ + p) * PSTR;
            float wgt = expf(pp[0] - M);
            L   += pp[1] * wgt;
            val += pp[2 + d] * wgt;
        }
        Us[d] = (L > 0.f) ? val / L : 0.f;
    }
    __syncthreads();
    int dd = tid >> 2, part = tid & 3;
    const __half* wr = g_Wh + (size_t)D_ * D_ + (size_t)(h * HD_ + dd) * D_ + part * 128;
    const float* u = Us + part * 128;
    float s = 0.f;
#pragma unroll 4
    for (int k = 0; k < 128; k += 8) {
        uint4 r = *(const uint4*)(wr + k);
        float w[8], dmy = 0.f;
        h8_unpack(r, w, dmy);
        s += w[0] * u[k]     + w[1] * u[k + 1] + w[2] * u[k + 2] + w[3] * u[k + 3]
           + w[4] * u[k + 4] + w[5] * u[k + 5] + w[6] * u[k + 6] + w[7] * u[k + 7];
    }
    s += __shfl_xor_sync(0xffffffffu, s, 1);
    s += __shfl_xor_sync(0xffffffffu, s, 2);
    if (part == 0) g_pt[(b * P_ + p) * D_ + h * HD_ + dd] = s;
}

// ---------------- 6. fused topk + MLP ----------------
__global__ __launch_bounds__(512) void tail_kernel(const float* __restrict__ W1,
                                                   const float* __restrict__ b1,
                                                   const float* __restrict__ W2,
                                                   const float* __restrict__ b2,
                                                   float* __restrict__ out) {
    __shared__ float ss[P_];
    __shared__ int idxs[TOPK_];
    __shared__ float zs[D_];
    __shared__ float hid[D_];
    int b = blockIdx.x, tid = threadIdx.x, w = tid >> 5, lane = tid & 31;

    // proto scores: 16 warps; warps 0..15 protos 0..15, warps 0..7 also 16..23
    for (int p = w; p < P_; p += 16) {
        const float* pr = g_pt + (b * P_ + p) * D_;
        float sq = 0.f;
#pragma unroll
        for (int j = 0; j < 16; j++) { float tv = pr[lane + 32 * j]; sq += tv * tv; }
#pragma unroll
        for (int o = 16; o > 0; o >>= 1) sq += __shfl_xor_sync(0xffffffffu, sq, o);
        if (lane == 0) ss[p] = sq;
    }
    __syncthreads();
    if (tid == 0) {
        unsigned used = 0;
        for (int i = 0; i < TOPK_; i++) {
            int best = -1; float bv = -3.4e38f;
            for (int p = 0; p < P_; p++)
                if (!((used >> p) & 1) && ss[p] > bv) { bv = ss[p]; best = p; }
            used |= 1u << best;
            idxs[i] = best;
        }
    }
    __syncthreads();
    {
        float s = 0.f;
        for (int i = 0; i < TOPK_; i++) s += g_pt[(b * P_ + idxs[i]) * D_ + tid];
        zs[tid] = s * (1.f / TOPK_);
    }
    __syncthreads();
    {
        const float* wr = W1 + (size_t)tid * D_;
        float s = b1[tid];
#pragma unroll 8
        for (int k = 0; k < D_; k += 4) {
            float4 w4 = *(const float4*)&wr[k];
            s += w4.x * zs[k] + w4.y * zs[k + 1] + w4.z * zs[k + 2] + w4.w * zs[k + 3];
        }
        hid[tid] = s / (1.f + expf(-s));
    }
    __syncthreads();
    {
        const float* wr = W2 + (size_t)tid * D_;
        float s = b2[tid];
#pragma unroll 8
        for (int k = 0; k < D_; k += 4) {
            float4 w4 = *(const float4*)&wr[k];
            s += w4.x * hid[k] + w4.y * hid[k + 1] + w4.z * hid[k + 2] + w4.w * hid[k + 3];
        }
        out[b * D_ + tid] = s;
    }
}

// ---------------- launch ----------------
extern "C" void kernel_launch(void* const* d_in, const int* in_sizes, int n_in,
                              void* d_out, int out_size) {
    (void)in_sizes; (void)n_in; (void)out_size;
    const float* x     = (const float*)d_in[0];
    const float* proto = (const float*)d_in[1];
    const float* ln_g  = (const float*)d_in[2];
    const float* ln_b  = (const float*)d_in[3];
    const float* Wq    = (const float*)d_in[4];
    const float* Wk    = (const float*)d_in[5];
    const float* Wv    = (const float*)d_in[6];
    const float* W1    = (const float*)d_in[7];
    const float* b1    = (const float*)d_in[8];
    const float* W2    = (const float*)d_in[9];
    const float* b2    = (const float*)d_in[10];
    float* out = (float*)d_out;

    cudaFuncSetAttribute(gemm_f16, cudaFuncAttributeMaxDynamicSharedMemorySize, GEMM_SMEM);
    cudaFuncSetAttribute(att_mma, cudaFuncAttributeMaxDynamicSharedMemorySize, ATT_SMEM);

    ln_kernel<<<(B_ * T_) / 8, 256>>>(x, ln_g, ln_b);
    round_w<<<(D_ * D_) / 256, 256>>>(Wk, Wv);
    qh_kernel<<<dim3(P_, H_), 512>>>(proto, Wq);
    gemm_f16<<<dim3(4, 512), 256, GEMM_SMEM>>>();
    att_mma<<<dim3(H_, NC_, B_), 256, ATT_SMEM>>>();
    mergeproj_kernel<<<dim3(P_, H_, B_), 512>>>();
    tail_kernel<<<B_, 512>>>(W1, b1, W2, b2, out);
}

// round 15
// speedup vs baseline: 1.0933x; 1.0933x over previous
#include <cuda_runtime.h>
#include <cuda_fp16.h>
#include <cstdint>
#include <cstddef>

#define B_    8
#define T_    8192
#define D_    512
#define H_    4
#define P_    24
#define HD_   128
#define TOPK_ 12
#define NC_   16
#define CHUNK_ 512
#define PSTR  514   // per-proto partial stride: m, l, U[512]

// ---------------- scratch (static device globals; no allocation) ----------------
__device__ __align__(16) __half g_xh[(size_t)B_ * T_ * D_];   // xn (fp16)
__device__ __align__(16) __half g_Wh[2 * D_ * D_];            // Wk, Wv (fp16)
__device__ __align__(16) __half g_K [(size_t)B_ * T_ * D_];   // K (fp16)
__device__ float g_Qh[H_ * P_ * HD_];
__device__ float g_part[(size_t)B_ * H_ * NC_ * P_ * PSTR];
__device__ float g_pt[B_ * P_ * D_];
__device__ float g_z [B_ * D_];
__device__ float g_hid[B_ * D_];

// ---------------- helpers ----------------
__device__ __forceinline__ uint32_t smem_u32(const void* p) {
    uint32_t a;
    asm("{ .reg .u64 t; cvta.to.shared.u64 t, %1; cvt.u32.u64 %0, t; }" : "=r"(a) : "l"(p));
    return a;
}
__device__ __forceinline__ void cp16(uint32_t s, const void* g) {
    asm volatile("cp.async.cg.shared.global [%0], [%1], 16;" :: "r"(s), "l"(g) : "memory");
}
__device__ __forceinline__ void cp_commit() {
    asm volatile("cp.async.commit_group;" ::: "memory");
}
template <int N> __device__ __forceinline__ void cp_wait() {
    asm volatile("cp.async.wait_group %0;" :: "n"(N) : "memory");
}
__device__ __forceinline__ void ldsm4(uint32_t& r0, uint32_t& r1, uint32_t& r2, uint32_t& r3,
                                      uint32_t addr) {
    asm volatile("ldmatrix.sync.aligned.m8n8.x4.shared.b16 {%0,%1,%2,%3}, [%4];"
                 : "=r"(r0), "=r"(r1), "=r"(r2), "=r"(r3) : "r"(addr));
}
__device__ __forceinline__ void ldsm4t(uint32_t& r0, uint32_t& r1, uint32_t& r2, uint32_t& r3,
                                       uint32_t addr) {
    asm volatile("ldmatrix.sync.aligned.m8n8.x4.trans.shared.b16 {%0,%1,%2,%3}, [%4];"
                 : "=r"(r0), "=r"(r1), "=r"(r2), "=r"(r3) : "r"(addr));
}
__device__ __forceinline__ void mma_f16(float* c,
                                        uint32_t a0, uint32_t a1, uint32_t a2, uint32_t a3,
                                        uint32_t b0, uint32_t b1) {
    asm volatile("mma.sync.aligned.m16n8k16.row.col.f32.f16.f16.f32 "
                 "{%0,%1,%2,%3}, {%4,%5,%6,%7}, {%8,%9}, {%0,%1,%2,%3};"
                 : "+f"(c[0]), "+f"(c[1]), "+f"(c[2]), "+f"(c[3])
                 : "r"(a0), "r"(a1), "r"(a2), "r"(a3), "r"(b0), "r"(b1));
}
__device__ __forceinline__ void h8_unpack(uint4 r, float* o, float& nn) {
    float2 f;
    f = __half22float2(*(__half2*)&r.x); o[0] = f.x; o[1] = f.y; nn += f.x * f.x + f.y * f.y;
    f = __half22float2(*(__half2*)&r.y); o[2] = f.x; o[3] = f.y; nn += f.x * f.x + f.y * f.y;
    f = __half22float2(*(__half2*)&r.z); o[4] = f.x; o[5] = f.y; nn += f.x * f.x + f.y * f.y;
    f = __half22float2(*(__half2*)&r.w); o[6] = f.x; o[7] = f.y; nn += f.x * f.x + f.y * f.y;
}

// ---------------- 1. LayerNorm -> fp16 ----------------
__global__ __launch_bounds__(256) void ln_kernel(const float* __restrict__ x,
                                                 const float* __restrict__ gw,
                                                 const float* __restrict__ bw) {
    int lane = threadIdx.x & 31;
    size_t row = (size_t)blockIdx.x * 8 + (threadIdx.x >> 5);
    const float* xr = x + row * D_;
    float4 v[4];
    float s = 0.f, sq = 0.f;
#pragma unroll
    for (int j = 0; j < 4; j++) {
        v[j] = *(const float4*)&xr[lane * 4 + j * 128];
        s  += v[j].x + v[j].y + v[j].z + v[j].w;
        sq += v[j].x * v[j].x + v[j].y * v[j].y + v[j].z * v[j].z + v[j].w * v[j].w;
    }
#pragma unroll
    for (int o = 16; o > 0; o >>= 1) {
        s  += __shfl_xor_sync(0xffffffffu, s,  o);
        sq += __shfl_xor_sync(0xffffffffu, sq, o);
    }
    float mu   = s * (1.f / 512.f);
    float var  = sq * (1.f / 512.f) - mu * mu;
    float rstd = rsqrtf(var + 1e-5f);
#pragma unroll
    for (int j = 0; j < 4; j++) {
        int c = lane * 4 + j * 128;
        float4 gv = *(const float4*)&gw[c];
        float4 bv = *(const float4*)&bw[c];
        __half h[4];
        h[0] = __float2half_rn((v[j].x - mu) * rstd * gv.x + bv.x);
        h[1] = __float2half_rn((v[j].y - mu) * rstd * gv.y + bv.y);
        h[2] = __float2half_rn((v[j].z - mu) * rstd * gv.z + bv.z);
        h[3] = __float2half_rn((v[j].w - mu) * rstd * gv.w + bv.w);
        *(uint2*)&g_xh[row * D_ + c] = *(uint2*)h;
    }
}

// ---------------- 1b. W matrices -> fp16 ----------------
__global__ __launch_bounds__(256) void round_w(const float* __restrict__ Wk,
                                               const float* __restrict__ Wv) {
    int i = blockIdx.x * 256 + threadIdx.x;
    g_Wh[i]           = __float2half_rn(Wk[i]);
    g_Wh[D_ * D_ + i] = __float2half_rn(Wv[i]);
}

// ---------------- 2. fp16 mma GEMM: K = xn @ Wk^T ----------------
#define ROWB 80
#define TILE_B (128 * ROWB)
#define STAGE_B (2 * TILE_B)
#define GEMM_SMEM (3 * STAGE_B)    // 61440 B

__global__ __launch_bounds__(256, 2) void gemm_f16() {
    extern __shared__ __align__(16) char smc[];
    const uint32_t sb = smem_u32(smc);

    const int tid = threadIdx.x;
    const int wid = tid >> 5, lane = tid & 31;
    const int n0 = blockIdx.x * 128;
    const size_t m0 = (size_t)blockIdx.y * 128;

    const __half* A_g = g_xh;
    const __half* B_g = g_Wh;           // Wk
    __half* C = g_K;

    const int lrow = tid >> 1;
    const int lch  = tid & 1;
    const size_t gA = (m0 + lrow) * D_ + lch * 16;
    const size_t gB = (size_t)(n0 + lrow) * D_ + lch * 16;
    const uint32_t sRow = (uint32_t)lrow * ROWB + lch * 32;

    const int wm = (wid >> 2) * 64;
    const int wn = (wid & 3) * 32;
    const int g  = lane >> 2;
    const int t  = lane & 3;

    uint32_t aRow[4], bRow[2];
#pragma unroll
    for (int mi = 0; mi < 4; mi++)
        aRow[mi] = (uint32_t)(wm + mi * 16 + (lane & 15)) * ROWB + ((lane & 16) ? 16 : 0);
#pragma unroll
    for (int np = 0; np < 2; np++)
        bRow[np] = (uint32_t)(wn + np * 16 + ((lane & 16) ? 8 : 0) + (lane & 7)) * ROWB
                   + ((lane & 8) ? 16 : 0);

    float c[4][4][4];
#pragma unroll
    for (int mi = 0; mi < 4; mi++)
#pragma unroll
        for (int ni = 0; ni < 4; ni++)
#pragma unroll
            for (int j = 0; j < 4; j++) c[mi][ni][j] = 0.f;

    auto stage = [&](int st, int kt) {
        uint32_t bbA = sb + (uint32_t)st * STAGE_B;
        uint32_t bbB = bbA + TILE_B;
        int ke = kt * 32;
        cp16(bbA + sRow,      A_g + gA + ke);
        cp16(bbA + sRow + 16, A_g + gA + ke + 8);
        cp16(bbB + sRow,      B_g + gB + ke);
        cp16(bbB + sRow + 16, B_g + gB + ke + 8);
        cp_commit();
    };

    stage(0, 0);
    stage(1, 1);

#pragma unroll 1
    for (int kt = 0; kt < 16; ++kt) {
        if (kt < 15) cp_wait<1>(); else cp_wait<0>();
        __syncthreads();
        if (kt + 2 < 16) stage((kt + 2) % 3, kt + 2);

        const uint32_t bbA = sb + (uint32_t)(kt % 3) * STAGE_B;
        const uint32_t bbB = bbA + TILE_B;

#pragma unroll
        for (int ks = 0; ks < 2; ks++) {
            const uint32_t ko = ks * 32;
            uint32_t a[4][4], bq[2][4];
#pragma unroll
            for (int mi = 0; mi < 4; mi++)
                ldsm4(a[mi][0], a[mi][1], a[mi][2], a[mi][3], bbA + aRow[mi] + ko);
#pragma unroll
            for (int np = 0; np < 2; np++)
                ldsm4(bq[np][0], bq[np][1], bq[np][2], bq[np][3], bbB + bRow[np] + ko);
#pragma unroll
            for (int mi = 0; mi < 4; mi++)
#pragma unroll
                for (int np = 0; np < 2; np++) {
                    mma_f16(c[mi][np * 2],     a[mi][0], a[mi][1], a[mi][2], a[mi][3],
                            bq[np][0], bq[np][1]);
                    mma_f16(c[mi][np * 2 + 1], a[mi][0], a[mi][1], a[mi][2], a[mi][3],
                            bq[np][2], bq[np][3]);
                }
        }
    }

#pragma unroll
    for (int mi = 0; mi < 4; mi++) {
#pragma unroll
        for (int ni = 0; ni < 4; ni++) {
            size_t r0 = m0 + wm + mi * 16 + g;
            int col = n0 + wn + ni * 8 + t * 2;
            *(__half2*)&C[r0 * D_ + col]       = __floats2half2_rn(c[mi][ni][0], c[mi][ni][1]);
            *(__half2*)&C[(r0 + 8) * D_ + col] = __floats2half2_rn(c[mi][ni][2], c[mi][ni][3]);
        }
    }
}

// ---------------- 3. Qh: grid (P, H), 512 threads ----------------
__global__ __launch_bounds__(512) void qh_kernel(const float* __restrict__ proto,
                                                 const float* __restrict__ Wq) {
    __shared__ float pr[D_];
    __shared__ float qp[HD_];
    __shared__ float sinv;
    int p = blockIdx.x, h = blockIdx.y, tid = threadIdx.x;
    pr[tid] = proto[p * D_ + tid];
    __syncthreads();
    int nl = tid >> 2, part = tid & 3;
    const float* wr = Wq + (size_t)(h * HD_ + nl) * D_ + part * 128;
    const float* pp = pr + part * 128;
    float a = 0.f;
#pragma unroll 8
    for (int k = 0; k < 128; k += 4) {
        float4 w4 = *(const float4*)&wr[k];
        a += w4.x * pp[k] + w4.y * pp[k + 1] + w4.z * pp[k + 2] + w4.w * pp[k + 3];
    }
    a += __shfl_xor_sync(0xffffffffu, a, 1);
    a += __shfl_xor_sync(0xffffffffu, a, 2);
    if (part == 0) qp[nl] = a;
    __syncthreads();
    if (tid < 32) {
        float sq = 0.f;
#pragma unroll
        for (int j = 0; j < 4; j++) { float tv = qp[tid + 32 * j]; sq += tv * tv; }
#pragma unroll
        for (int o = 16; o > 0; o >>= 1) sq += __shfl_xor_sync(0xffffffffu, sq, o);
        if (tid == 0) sinv = 1.f / fmaxf(sqrtf(sq), 1e-12f);
    }
    __syncthreads();
    if (tid < HD_) g_Qh[(h * P_ + p) * HD_ + tid] = qp[tid] * sinv;
}

// ---------------- 4. attention (R13 version: scalar frag loads, ldsm4t for V) ----------------
// grid (H, NC, B), 256 threads. smem 113920 B -> 2 CTAs/SM.
#define oQ   0
#define oKB  8704
#define KBUF 34816
#define oSP  78336
#define oNm  111616
#define oMs  113664
#define oLs  113792
#define ATT_SMEM 113920

__global__ __launch_bounds__(256, 2) void att_mma() {
    extern __shared__ __align__(16) char smc[];
    const uint32_t sb = smem_u32(smc);
    __half* Qs = (__half*)(smc + oQ);
    __half* SP = (__half*)(smc + oSP);     // scores then exp-weights, fp16, 32 x 520
    float*  Nm = (float*)(smc + oNm);
    float*  Ms = (float*)(smc + oMs);
    float*  Ls = (float*)(smc + oLs);
    const uint32_t* Qw = (const uint32_t*)Qs;
    const uint32_t* Pw = (const uint32_t*)SP;

    const int tid = threadIdx.x;
    const int wid = tid >> 5, lane = tid & 31;
    const int g = lane >> 2, t = lane & 3;
    const int h = blockIdx.x, cz = blockIdx.y, b = blockIdx.z;
    const size_t tokbase = (size_t)(b * T_ + cz * CHUNK_);

    for (int i = tid; i < 32 * 128; i += 256) {
        int p = i >> 7, d = i & 127;
        float v = (p < P_) ? g_Qh[(h * P_ + p) * HD_ + d] : 0.f;
        Qs[p * 136 + d] = __float2half_rn(v);
    }

    auto stageK = [&](int st, int bf) {
        uint32_t bb = sb + oKB + (uint32_t)bf * KBUF;
#pragma unroll
        for (int j = 0; j < 8; j++) {
            int lin = tid + 256 * j;
            int tok = lin >> 4, ch = lin & 15;
            cp16(bb + (uint32_t)(tok * 136 + ch * 8) * 2,
                 g_K + (tokbase + st * 128 + tok) * D_ + h * HD_ + ch * 8);
        }
        cp_commit();
    };
    auto stageXN = [&](int dg, int st, int bf) {
        uint32_t bb = sb + oKB + (uint32_t)bf * KBUF;
#pragma unroll
        for (int j = 0; j < 8; j++) {
            int lin = tid + 256 * j;
            int tok = lin >> 4, ch = lin & 15;
            cp16(bb + (uint32_t)(tok * 136 + ch * 8) * 2,
                 g_xh + (tokbase + st * 128 + tok) * D_ + dg * 128 + ch * 8);
        }
        cp_commit();
    };

    stageK(0, 0);
    stageK(1, 1);

    // ================= scores (fp16 into SP) =================
#pragma unroll 1
    for (int st = 0; st < 4; ++st) {
        cp_wait<1>();
        __syncthreads();
        const __half*   Kh = (const __half*)(smc + oKB + (st & 1) * KBUF);
        const uint32_t* Kw = (const uint32_t*)Kh;

        {
            int tok = tid >> 1, hf = tid & 1;
            const uint4* kp = (const uint4*)(Kh + tok * 136 + hf * 64);
            float nn = 0.f, tmp[8];
#pragma unroll
            for (int i = 0; i < 8; i++) h8_unpack(kp[i], tmp, nn);
            nn += __shfl_xor_sync(0xffffffffu, nn, 1);
            if (hf == 0) Nm[st * 128 + tok] = nn;
        }
        __syncthreads();

        float c[2][2][4] = {};
#pragma unroll
        for (int kt = 0; kt < 8; kt++) {
            uint32_t a[2][4];
#pragma unroll
            for (int mi = 0; mi < 2; mi++) {
                int base = (mi * 16 + g) * 68 + kt * 8 + t;
                a[mi][0] = Qw[base];
                a[mi][1] = Qw[base + 8 * 68];
                a[mi][2] = Qw[base + 4];
                a[mi][3] = Qw[base + 8 * 68 + 4];
            }
#pragma unroll
            for (int np = 0; np < 2; np++) {
                int tok = wid * 16 + np * 8 + g;
                int base = tok * 68 + kt * 8 + t;
                uint32_t b0 = Kw[base], b1 = Kw[base + 4];
#pragma unroll
                for (int mi = 0; mi < 2; mi++)
                    mma_f16(c[mi][np], a[mi][0], a[mi][1], a[mi][2], a[mi][3], b0, b1);
            }
        }
#pragma unroll
        for (int np = 0; np < 2; np++) {
            int tc = wid * 16 + np * 8 + t * 2;
            float inv0 = 1.f / (fmaxf(sqrtf(Nm[st * 128 + tc]),     1e-12f) * 0.07f);
            float inv1 = 1.f / (fmaxf(sqrtf(Nm[st * 128 + tc + 1]), 1e-12f) * 0.07f);
#pragma unroll
            for (int mi = 0; mi < 2; mi++) {
                int r0 = mi * 16 + g;
                *(__half2*)&SP[r0 * 520 + st * 128 + tc] =
                    __floats2half2_rn(c[mi][np][0] * inv0, c[mi][np][1] * inv1);
                *(__half2*)&SP[(r0 + 8) * 520 + st * 128 + tc] =
                    __floats2half2_rn(c[mi][np][2] * inv0, c[mi][np][3] * inv1);
            }
        }
        __syncthreads();
        if (st < 2) stageK(st + 2, st & 1);
        else        stageXN(0, st - 2, st & 1);   // PV stages ls=0,1
    }

    // ================= softmax in place on SP =================
#pragma unroll 1
    for (int rr = 0; rr < 4; ++rr) {
        int p = wid + rr * 8;
        float vals[16];
        float m = -3.4e38f;
#pragma unroll
        for (int j = 0; j < 16; j++) {
            vals[j] = __half2float(SP[p * 520 + lane + 32 * j]);
            m = fmaxf(m, vals[j]);
        }
#pragma unroll
        for (int o = 16; o > 0; o >>= 1) m = fmaxf(m, __shfl_xor_sync(0xffffffffu, m, o));
        float s = 0.f;
#pragma unroll
        for (int j = 0; j < 16; j++) {
            float e = expf(vals[j] - m);
            SP[p * 520 + lane + 32 * j] = __float2half_rn(e);
            s += e;
        }
#pragma unroll
        for (int o = 16; o > 0; o >>= 1) s += __shfl_xor_sync(0xffffffffu, s, o);
        if (lane == 0) { Ms[p] = m; Ls[p] = s; }
    }

    // ================= PV: U = P @ xn =================
    size_t base = (((size_t)(b * H_ + h) * NC_ + cz) * P_) * PSTR;
    float cp2[2][2][4] = {};
#pragma unroll 1
    for (int ls = 0; ls < 16; ++ls) {
        int dg = ls >> 2, st = ls & 3;
        if (ls < 15) cp_wait<1>(); else cp_wait<0>();
        __syncthreads();
        uint32_t vb = sb + oKB + (uint32_t)(ls & 1) * KBUF;

#pragma unroll
        for (int kt = 0; kt < 8; kt++) {
            uint32_t a[2][4];
#pragma unroll
            for (int mi = 0; mi < 2; mi++) {
                int abase = (mi * 16 + g) * 260 + st * 64 + kt * 8 + t;
                a[mi][0] = Pw[abase];
                a[mi][1] = Pw[abase + 8 * 260];
                a[mi][2] = Pw[abase + 4];
                a[mi][3] = Pw[abase + 8 * 260 + 4];
            }
            uint32_t r0, r1, r2, r3;
            uint32_t addr = vb + (uint32_t)((kt * 16 + (lane & 15)) * 136 +
                                            wid * 16 + ((lane & 16) ? 8 : 0)) * 2;
            ldsm4t(r0, r1, r2, r3, addr);
#pragma unroll
            for (int mi = 0; mi < 2; mi++) {
                mma_f16(cp2[mi][0], a[mi][0], a[mi][1], a[mi][2], a[mi][3], r0, r1);
                mma_f16(cp2[mi][1], a[mi][0], a[mi][1], a[mi][2], a[mi][3], r2, r3);
            }
        }
        __syncthreads();
        if (ls + 2 < 16) stageXN((ls + 2) >> 2, (ls + 2) & 3, ls & 1);

        if (st == 3) {
#pragma unroll
            for (int mi = 0; mi < 2; mi++)
#pragma unroll
                for (int np = 0; np < 2; np++)
#pragma unroll
                    for (int j = 0; j < 4; j++) {
                        int r = mi * 16 + g + ((j >> 1) ? 8 : 0);
                        if (r < P_) {
                            int col = dg * 128 + wid * 16 + np * 8 + t * 2 + (j & 1);
                            g_part[base + (size_t)r * PSTR + 2 + col] = cp2[mi][np][j];
                        }
                        cp2[mi][np][j] = 0.f;
                    }
        }
    }
    if (tid < P_) {
        g_part[base + (size_t)tid * PSTR]     = Ms[tid];
        g_part[base + (size_t)tid * PSTR + 1] = Ls[tid];
    }
}

// ---------------- 5. fused merge + Wv projection -> proto_tokens ----------------
__global__ __launch_bounds__(512) void mergeproj_kernel() {
    __shared__ float Us[D_];
    int p = blockIdx.x, h = blockIdx.y, b = blockIdx.z;
    int tid = threadIdx.x;
    {
        int d = tid;
        float M = -3.4e38f;
        for (int c = 0; c < NC_; c++) {
            const float* pp = g_part + (((size_t)(b * H_ + h) * NC_ + c) * P_ + p) * PSTR;
            M = fmaxf(M, pp[0]);
        }
        float L = 0.f, val = 0.f;
        for (int c = 0; c < NC_; c++) {
            const float* pp = g_part + (((size_t)(b * H_ + h) * NC_ + c) * P_ + p) * PSTR;
            float wgt = expf(pp[0] - M);
            L   += pp[1] * wgt;
            val += pp[2 + d] * wgt;
        }
        Us[d] = (L > 0.f) ? val / L : 0.f;
    }
    __syncthreads();
    int dd = tid >> 2, part = tid & 3;
    const __half* wr = g_Wh + (size_t)D_ * D_ + (size_t)(h * HD_ + dd) * D_ + part * 128;
    const float* u = Us + part * 128;
    float s = 0.f;
#pragma unroll 4
    for (int k = 0; k < 128; k += 8) {
        uint4 r = *(const uint4*)(wr + k);
        float w[8], dmy = 0.f;
        h8_unpack(r, w, dmy);
        s += w[0] * u[k]     + w[1] * u[k + 1] + w[2] * u[k + 2] + w[3] * u[k + 3]
           + w[4] * u[k + 4] + w[5] * u[k + 5] + w[6] * u[k + 6] + w[7] * u[k + 7];
    }
    s += __shfl_xor_sync(0xffffffffu, s, 1);
    s += __shfl_xor_sync(0xffffffffu, s, 2);
    if (part == 0) g_pt[(b * P_ + p) * D_ + h * HD_ + dd] = s;
}

// ---------------- 6. topk ----------------
__global__ __launch_bounds__(256) void topk_kernel() {
    int b = blockIdx.x, tid = threadIdx.x, w = tid >> 5, lane = tid & 31;
    __shared__ float ss[P_];
    __shared__ int idxs[TOPK_];
#pragma unroll 1
    for (int rr = 0; rr < 3; rr++) {
        int p = w + rr * 8;
        const float* pr = g_pt + (b * P_ + p) * D_;
        float sq = 0.f;
#pragma unroll
        for (int j = 0; j < 16; j++) { float tv = pr[lane + 32 * j]; sq += tv * tv; }
#pragma unroll
        for (int o = 16; o > 0; o >>= 1) sq += __shfl_xor_sync(0xffffffffu, sq, o);
        if (lane == 0) ss[p] = sq;
    }
    __syncthreads();
    if (tid == 0) {
        unsigned used = 0;
        for (int i = 0; i < TOPK_; i++) {
            int best = -1; float bv = -3.4e38f;
            for (int p = 0; p < P_; p++)
                if (!((used >> p) & 1) && ss[p] > bv) { bv = ss[p]; best = p; }
            used |= 1u << best;
            idxs[i] = best;
        }
    }
    __syncthreads();
    for (int d = tid; d < D_; d += 256) {
        float s = 0.f;
        for (int i = 0; i < TOPK_; i++) s += g_pt[(b * P_ + idxs[i]) * D_ + d];
        g_z[b * D_ + d] = s * (1.f / TOPK_);
    }
}

// ---------------- 7. MLP ----------------
__global__ __launch_bounds__(128) void mlp_kernel(int in_sel, const float* __restrict__ W,
                                                  const float* __restrict__ bias,
                                                  float* __restrict__ out_ext, int act) {
    __shared__ float zs[D_];
    int b = blockIdx.y, tid = threadIdx.x;
    int n = blockIdx.x * 128 + tid;
    const float* in = in_sel ? g_hid : g_z;
    for (int i = tid; i < D_; i += 128) zs[i] = in[b * D_ + i];
    __syncthreads();
    const float* wr = W + (size_t)n * D_;
    float s = bias[n];
    for (int k = 0; k < D_; k += 4) {
        float4 w4 = *(const float4*)&wr[k];
        s += w4.x * zs[k] + w4.y * zs[k + 1] + w4.z * zs[k + 2] + w4.w * zs[k + 3];
    }
    if (act) s = s / (1.f + expf(-s));
    float* out = out_ext ? out_ext : g_hid;
    out[b * D_ + n] = s;
}

// ---------------- launch ----------------
extern "C" void kernel_launch(void* const* d_in, const int* in_sizes, int n_in,
                              void* d_out, int out_size) {
    (void)in_sizes; (void)n_in; (void)out_size;
    const float* x     = (const float*)d_in[0];
    const float* proto = (const float*)d_in[1];
    const float* ln_g  = (const float*)d_in[2];
    const float* ln_b  = (const float*)d_in[3];
    const float* Wq    = (const float*)d_in[4];
    const float* Wk    = (const float*)d_in[5];
    const float* Wv    = (const float*)d_in[6];
    const float* W1    = (const float*)d_in[7];
    const float* b1    = (const float*)d_in[8];
    const float* W2    = (const float*)d_in[9];
    const float* b2    = (const float*)d_in[10];
    float* out = (float*)d_out;

    cudaFuncSetAttribute(gemm_f16, cudaFuncAttributeMaxDynamicSharedMemorySize, GEMM_SMEM);
    cudaFuncSetAttribute(att_mma, cudaFuncAttributeMaxDynamicSharedMemorySize, ATT_SMEM);

    ln_kernel<<<(B_ * T_) / 8, 256>>>(x, ln_g, ln_b);
    round_w<<<(D_ * D_) / 256, 256>>>(Wk, Wv);
    qh_kernel<<<dim3(P_, H_), 512>>>(proto, Wq);
    gemm_f16<<<dim3(4, 512), 256, GEMM_SMEM>>>();
    att_mma<<<dim3(H_, NC_, B_), 256, ATT_SMEM>>>();
    mergeproj_kernel<<<dim3(P_, H_, B_), 512>>>();
    topk_kernel<<<B_, 256>>>();
    mlp_kernel<<<dim3(4, B_), 128>>>(0, W1, b1, nullptr, 1);
    mlp_kernel<<<dim3(4, B_), 128>>>(1, W2, b2, out, 0);
}

// round 16
// speedup vs baseline: 1.1656x; 1.0662x over previous
#include <cuda_runtime.h>
#include <cuda_fp16.h>
#include <cstdint>
#include <cstddef>

#define B_    8
#define T_    8192
#define D_    512
#define H_    4
#define P_    24
#define HD_   128
#define TOPK_ 12
#define NC_   16
#define CHUNK_ 512
#define PSTR  514   // per-proto partial stride: m, l, U[512]

// ---------------- scratch (static device globals; no allocation) ----------------
__device__ __align__(16) __half g_xh[(size_t)B_ * T_ * D_];   // xn (fp16)
__device__ __align__(16) __half g_Wh[2 * D_ * D_];            // Wk, Wv (fp16)
__device__ __align__(16) __half g_S [(size_t)B_ * H_ * P_ * T_];  // scores (fp16)
__device__ float g_Qh[H_ * P_ * HD_];
__device__ float g_part[(size_t)B_ * H_ * NC_ * P_ * PSTR];
__device__ float g_U [(size_t)B_ * H_ * P_ * D_];
__device__ float g_pt[B_ * P_ * D_];
__device__ float g_z [B_ * D_];
__device__ float g_hid[B_ * D_];

// ---------------- helpers ----------------
__device__ __forceinline__ uint32_t smem_u32(const void* p) {
    uint32_t a;
    asm("{ .reg .u64 t; cvta.to.shared.u64 t, %1; cvt.u32.u64 %0, t; }" : "=r"(a) : "l"(p));
    return a;
}
__device__ __forceinline__ void cp16(uint32_t s, const void* g) {
    asm volatile("cp.async.cg.shared.global [%0], [%1], 16;" :: "r"(s), "l"(g) : "memory");
}
__device__ __forceinline__ void cp_commit() {
    asm volatile("cp.async.commit_group;" ::: "memory");
}
template <int N> __device__ __forceinline__ void cp_wait() {
    asm volatile("cp.async.wait_group %0;" :: "n"(N) : "memory");
}
__device__ __forceinline__ void ldsm4(uint32_t& r0, uint32_t& r1, uint32_t& r2, uint32_t& r3,
                                      uint32_t addr) {
    asm volatile("ldmatrix.sync.aligned.m8n8.x4.shared.b16 {%0,%1,%2,%3}, [%4];"
                 : "=r"(r0), "=r"(r1), "=r"(r2), "=r"(r3) : "r"(addr));
}
__device__ __forceinline__ void ldsm4t(uint32_t& r0, uint32_t& r1, uint32_t& r2, uint32_t& r3,
                                       uint32_t addr) {
    asm volatile("ldmatrix.sync.aligned.m8n8.x4.trans.shared.b16 {%0,%1,%2,%3}, [%4];"
                 : "=r"(r0), "=r"(r1), "=r"(r2), "=r"(r3) : "r"(addr));
}
__device__ __forceinline__ void mma_f16(float* c,
                                        uint32_t a0, uint32_t a1, uint32_t a2, uint32_t a3,
                                        uint32_t b0, uint32_t b1) {
    asm volatile("mma.sync.aligned.m16n8k16.row.col.f32.f16.f16.f32 "
                 "{%0,%1,%2,%3}, {%4,%5,%6,%7}, {%8,%9}, {%0,%1,%2,%3};"
                 : "+f"(c[0]), "+f"(c[1]), "+f"(c[2]), "+f"(c[3])
                 : "r"(a0), "r"(a1), "r"(a2), "r"(a3), "r"(b0), "r"(b1));
}
__device__ __forceinline__ void h8_unpack(uint4 r, float* o, float& nn) {
    float2 f;
    f = __half22float2(*(__half2*)&r.x); o[0] = f.x; o[1] = f.y; nn += f.x * f.x + f.y * f.y;
    f = __half22float2(*(__half2*)&r.y); o[2] = f.x; o[3] = f.y; nn += f.x * f.x + f.y * f.y;
    f = __half22float2(*(__half2*)&r.z); o[4] = f.x; o[5] = f.y; nn += f.x * f.x + f.y * f.y;
    f = __half22float2(*(__half2*)&r.w); o[6] = f.x; o[7] = f.y; nn += f.x * f.x + f.y * f.y;
}

// ---------------- 1. LayerNorm -> fp16 ----------------
__global__ __launch_bounds__(256) void ln_kernel(const float* __restrict__ x,
                                                 const float* __restrict__ gw,
                                                 const float* __restrict__ bw) {
    int lane = threadIdx.x & 31;
    size_t row = (size_t)blockIdx.x * 8 + (threadIdx.x >> 5);
    const float* xr = x + row * D_;
    float4 v[4];
    float s = 0.f, sq = 0.f;
#pragma unroll
    for (int j = 0; j < 4; j++) {
        v[j] = *(const float4*)&xr[lane * 4 + j * 128];
        s  += v[j].x + v[j].y + v[j].z + v[j].w;
        sq += v[j].x * v[j].x + v[j].y * v[j].y + v[j].z * v[j].z + v[j].w * v[j].w;
    }
#pragma unroll
    for (int o = 16; o > 0; o >>= 1) {
        s  += __shfl_xor_sync(0xffffffffu, s,  o);
        sq += __shfl_xor_sync(0xffffffffu, sq, o);
    }
    float mu   = s * (1.f / 512.f);
    float var  = sq * (1.f / 512.f) - mu * mu;
    float rstd = rsqrtf(var + 1e-5f);
#pragma unroll
    for (int j = 0; j < 4; j++) {
        int c = lane * 4 + j * 128;
        float4 gv = *(const float4*)&gw[c];
        float4 bv = *(const float4*)&bw[c];
        __half h[4];
        h[0] = __float2half_rn((v[j].x - mu) * rstd * gv.x + bv.x);
        h[1] = __float2half_rn((v[j].y - mu) * rstd * gv.y + bv.y);
        h[2] = __float2half_rn((v[j].z - mu) * rstd * gv.z + bv.z);
        h[3] = __float2half_rn((v[j].w - mu) * rstd * gv.w + bv.w);
        *(uint2*)&g_xh[row * D_ + c] = *(uint2*)h;
    }
}

// ---------------- 1b. W matrices -> fp16 ----------------
__global__ __launch_bounds__(256) void round_w(const float* __restrict__ Wk,
                                               const float* __restrict__ Wv) {
    int i = blockIdx.x * 256 + threadIdx.x;
    g_Wh[i]           = __float2half_rn(Wk[i]);
    g_Wh[D_ * D_ + i] = __float2half_rn(Wv[i]);
}

// ---------------- 3. Qh: grid (P, H), 512 threads ----------------
__global__ __launch_bounds__(512) void qh_kernel(const float* __restrict__ proto,
                                                 const float* __restrict__ Wq) {
    __shared__ float pr[D_];
    __shared__ float qp[HD_];
    __shared__ float sinv;
    int p = blockIdx.x, h = blockIdx.y, tid = threadIdx.x;
    pr[tid] = proto[p * D_ + tid];
    __syncthreads();
    int nl = tid >> 2, part = tid & 3;
    const float* wr = Wq + (size_t)(h * HD_ + nl) * D_ + part * 128;
    const float* pp = pr + part * 128;
    float a = 0.f;
#pragma unroll 8
    for (int k = 0; k < 128; k += 4) {
        float4 w4 = *(const float4*)&wr[k];
        a += w4.x * pp[k] + w4.y * pp[k + 1] + w4.z * pp[k + 2] + w4.w * pp[k + 3];
    }
    a += __shfl_xor_sync(0xffffffffu, a, 1);
    a += __shfl_xor_sync(0xffffffffu, a, 2);
    if (part == 0) qp[nl] = a;
    __syncthreads();
    if (tid < 32) {
        float sq = 0.f;
#pragma unroll
        for (int j = 0; j < 4; j++) { float tv = qp[tid + 32 * j]; sq += tv * tv; }
#pragma unroll
        for (int o = 16; o > 0; o >>= 1) sq += __shfl_xor_sync(0xffffffffu, sq, o);
        if (tid == 0) sinv = 1.f / fmaxf(sqrtf(sq), 1e-12f);
    }
    __syncthreads();
    if (tid < HD_) g_Qh[(h * P_ + p) * HD_ + tid] = qp[tid] * sinv;
}

// ---------------- 2. fused GEMM + scores: S = Qh . norm(K) / TEMP ----------------
// grid (H, 512): x = head, y = token tile (b = y>>6, tok0 = (y&63)*128).
#define ROWB 80
#define TILE_B (128 * ROWB)
#define STAGE_B (2 * TILE_B)
#define GEMM_SMEM (3 * STAGE_B)    // 61440 B
// epilogue smem layout (within same 61440 B, reused after mainloop):
#define eKT 0          // K tile fp16: 128 x 136 halves = 34816 B
#define eQ  34816      // Q fp16: 32 x 136 halves = 8704 B
#define eNm 43520      // 128 floats

__global__ __launch_bounds__(256, 2) void gemm_ks() {
    extern __shared__ __align__(16) char smc[];
    const uint32_t sb = smem_u32(smc);

    const int tid = threadIdx.x;
    const int wid = tid >> 5, lane = tid & 31;
    const int h  = blockIdx.x;
    const int n0 = h * 128;
    const size_t m0 = (size_t)blockIdx.y * 128;
    const int b    = blockIdx.y >> 6;
    const int tok0 = (blockIdx.y & 63) * 128;

    const __half* A_g = g_xh;
    const __half* B_g = g_Wh;           // Wk

    const int lrow = tid >> 1;
    const int lch  = tid & 1;
    const size_t gA = (m0 + lrow) * D_ + lch * 16;
    const size_t gB = (size_t)(n0 + lrow) * D_ + lch * 16;
    const uint32_t sRow = (uint32_t)lrow * ROWB + lch * 32;

    const int wm = (wid >> 2) * 64;
    const int wn = (wid & 3) * 32;
    const int g  = lane >> 2;
    const int t  = lane & 3;

    uint32_t aRow[4], bRow[2];
#pragma unroll
    for (int mi = 0; mi < 4; mi++)
        aRow[mi] = (uint32_t)(wm + mi * 16 + (lane & 15)) * ROWB + ((lane & 16) ? 16 : 0);
#pragma unroll
    for (int np = 0; np < 2; np++)
        bRow[np] = (uint32_t)(wn + np * 16 + ((lane & 16) ? 8 : 0) + (lane & 7)) * ROWB
                   + ((lane & 8) ? 16 : 0);

    float c[4][4][4];
#pragma unroll
    for (int mi = 0; mi < 4; mi++)
#pragma unroll
        for (int ni = 0; ni < 4; ni++)
#pragma unroll
            for (int j = 0; j < 4; j++) c[mi][ni][j] = 0.f;

    auto stage = [&](int st, int kt) {
        uint32_t bbA = sb + (uint32_t)st * STAGE_B;
        uint32_t bbB = bbA + TILE_B;
        int ke = kt * 32;
        cp16(bbA + sRow,      A_g + gA + ke);
        cp16(bbA + sRow + 16, A_g + gA + ke + 8);
        cp16(bbB + sRow,      B_g + gB + ke);
        cp16(bbB + sRow + 16, B_g + gB + ke + 8);
        cp_commit();
    };

    stage(0, 0);
    stage(1, 1);

#pragma unroll 1
    for (int kt = 0; kt < 16; ++kt) {
        if (kt < 15) cp_wait<1>(); else cp_wait<0>();
        __syncthreads();
        if (kt + 2 < 16) stage((kt + 2) % 3, kt + 2);

        const uint32_t bbA = sb + (uint32_t)(kt % 3) * STAGE_B;
        const uint32_t bbB = bbA + TILE_B;

#pragma unroll
        for (int ks = 0; ks < 2; ks++) {
            const uint32_t ko = ks * 32;
            uint32_t a[4][4], bq[2][4];
#pragma unroll
            for (int mi = 0; mi < 4; mi++)
                ldsm4(a[mi][0], a[mi][1], a[mi][2], a[mi][3], bbA + aRow[mi] + ko);
#pragma unroll
            for (int np = 0; np < 2; np++)
                ldsm4(bq[np][0], bq[np][1], bq[np][2], bq[np][3], bbB + bRow[np] + ko);
#pragma unroll
            for (int mi = 0; mi < 4; mi++)
#pragma unroll
                for (int np = 0; np < 2; np++) {
                    mma_f16(c[mi][np * 2],     a[mi][0], a[mi][1], a[mi][2], a[mi][3],
                            bq[np][0], bq[np][1]);
                    mma_f16(c[mi][np * 2 + 1], a[mi][0], a[mi][1], a[mi][2], a[mi][3],
                            bq[np][2], bq[np][3]);
                }
        }
    }
    __syncthreads();                    // all reads of stage buffers done

    // ---- epilogue: K tile -> smem fp16 (rows=tokens, cols=head dims) ----
    __half* Kt = (__half*)(smc + eKT);
    __half* Qs = (__half*)(smc + eQ);
    float*  Nm = (float*)(smc + eNm);
#pragma unroll
    for (int mi = 0; mi < 4; mi++)
#pragma unroll
        for (int ni = 0; ni < 4; ni++) {
            int r0 = wm + mi * 16 + g;
            int col = wn + ni * 8 + t * 2;
            *(__half2*)&Kt[r0 * 136 + col]       = __floats2half2_rn(c[mi][ni][0], c[mi][ni][1]);
            *(__half2*)&Kt[(r0 + 8) * 136 + col] = __floats2half2_rn(c[mi][ni][2], c[mi][ni][3]);
        }
    // load Q (fp16, rows >= 24 zero)
    for (int i = tid; i < 32 * 128; i += 256) {
        int p = i >> 7, d = i & 127;
        float v = (p < P_) ? g_Qh[(h * P_ + p) * HD_ + d] : 0.f;
        Qs[p * 136 + d] = __float2half_rn(v);
    }
    __syncthreads();

    // per-token norms (2 threads per token)
    {
        int tok = tid >> 1, hf = tid & 1;
        const uint4* kp = (const uint4*)(Kt + tok * 136 + hf * 64);
        float nn = 0.f, tmp[8];
#pragma unroll
        for (int i = 0; i < 8; i++) h8_unpack(kp[i], tmp, nn);
        nn += __shfl_xor_sync(0xffffffffu, nn, 1);
        if (hf == 0) Nm[tok] = nn;
    }
    __syncthreads();

    // score mma: S[p][tok] = Qh[p] . Kt[tok] (R13 att layout, wid 0..7 -> tok 0..127)
    const uint32_t* Qw = (const uint32_t*)Qs;
    const uint32_t* Kw = (const uint32_t*)Kt;
    float c2[2][2][4] = {};
#pragma unroll
    for (int kt = 0; kt < 8; kt++) {
        uint32_t a[2][4];
#pragma unroll
        for (int mi = 0; mi < 2; mi++) {
            int base = (mi * 16 + g) * 68 + kt * 8 + t;
            a[mi][0] = Qw[base];
            a[mi][1] = Qw[base + 8 * 68];
            a[mi][2] = Qw[base + 4];
            a[mi][3] = Qw[base + 8 * 68 + 4];
        }
#pragma unroll
        for (int np = 0; np < 2; np++) {
            int tok = wid * 16 + np * 8 + g;
            int base = tok * 68 + kt * 8 + t;
            uint32_t b0 = Kw[base], b1 = Kw[base + 4];
#pragma unroll
            for (int mi = 0; mi < 2; mi++)
                mma_f16(c2[mi][np], a[mi][0], a[mi][1], a[mi][2], a[mi][3], b0, b1);
        }
    }
#pragma unroll
    for (int np = 0; np < 2; np++) {
        int tc = wid * 16 + np * 8 + t * 2;
        float inv0 = 1.f / (fmaxf(sqrtf(Nm[tc]),     1e-12f) * 0.07f);
        float inv1 = 1.f / (fmaxf(sqrtf(Nm[tc + 1]), 1e-12f) * 0.07f);
#pragma unroll
        for (int mi = 0; mi < 2; mi++) {
            int r0 = mi * 16 + g;
            if (r0 < P_)
                *(__half2*)&g_S[((size_t)(b * H_ + h) * P_ + r0) * T_ + tok0 + tc] =
                    __floats2half2_rn(c2[mi][np][0] * inv0, c2[mi][np][1] * inv1);
            if (r0 + 8 < P_)
                *(__half2*)&g_S[((size_t)(b * H_ + h) * P_ + r0 + 8) * T_ + tok0 + tc] =
                    __floats2half2_rn(c2[mi][np][2] * inv0, c2[mi][np][3] * inv1);
        }
    }
}

// ---------------- 4. attention: softmax + PV only ----------------
// grid (H, NC, B), 256 threads. smem 103168 B -> 2 CTAs/SM.
#define oKB  0
#define KBUF 34816
#define oSP  69632
#define oMs  102912
#define oLs  103040
#define ATT_SMEM 103168

__global__ __launch_bounds__(256, 2) void att_mma() {
    extern __shared__ __align__(16) char smc[];
    const uint32_t sb = smem_u32(smc);
    __half* SP = (__half*)(smc + oSP);     // scores then exp-weights, fp16, 32 x 520
    float*  Ms = (float*)(smc + oMs);
    float*  Ls = (float*)(smc + oLs);
    const uint32_t* Pw = (const uint32_t*)SP;

    const int tid = threadIdx.x;
    const int wid = tid >> 5, lane = tid & 31;
    const int g = lane >> 2, t = lane & 3;
    const int h = blockIdx.x, cz = blockIdx.y, b = blockIdx.z;
    const size_t tokbase = (size_t)(b * T_ + cz * CHUNK_);

    auto stageXN = [&](int dg, int st, int bf) {
        uint32_t bb = sb + oKB + (uint32_t)bf * KBUF;
#pragma unroll
        for (int j = 0; j < 8; j++) {
            int lin = tid + 256 * j;
            int tok = lin >> 4, ch = lin & 15;
            cp16(bb + (uint32_t)(tok * 136 + ch * 8) * 2,
                 g_xh + (tokbase + st * 128 + tok) * D_ + dg * 128 + ch * 8);
        }
        cp_commit();
    };

    // stage scores (24 rows x 512 tokens)
    {
        const __half* src = g_S + (size_t)(b * H_ + h) * P_ * T_ + cz * CHUNK_;
#pragma unroll
        for (int j = 0; j < 6; j++) {
            int lin = tid + 256 * j;         // 0..1535
            int row = lin >> 6, ch = lin & 63;
            cp16(sb + oSP + (uint32_t)(row * 520 + ch * 8) * 2,
                 src + (size_t)row * T_ + ch * 8);
        }
        cp_commit();
    }
    stageXN(0, 0, 0);
    stageXN(0, 1, 1);

    cp_wait<2>();        // scores landed
    __syncthreads();

    // ================= softmax in place on SP (rows 0..23) =================
#pragma unroll 1
    for (int rr = 0; rr < 3; ++rr) {
        int p = wid + rr * 8;
        float vals[16];
        float m = -3.4e38f;
#pragma unroll
        for (int j = 0; j < 16; j++) {
            vals[j] = __half2float(SP[p * 520 + lane + 32 * j]);
            m = fmaxf(m, vals[j]);
        }
#pragma unroll
        for (int o = 16; o > 0; o >>= 1) m = fmaxf(m, __shfl_xor_sync(0xffffffffu, m, o));
        float s = 0.f;
#pragma unroll
        for (int j = 0; j < 16; j++) {
            float e = expf(vals[j] - m);
            SP[p * 520 + lane + 32 * j] = __float2half_rn(e);
            s += e;
        }
#pragma unroll
        for (int o = 16; o > 0; o >>= 1) s += __shfl_xor_sync(0xffffffffu, s, o);
        if (lane == 0) { Ms[p] = m; Ls[p] = s; }
    }

    // ================= PV: U = P @ xn =================
    size_t base = (((size_t)(b * H_ + h) * NC_ + cz) * P_) * PSTR;
    float cp2[2][2][4] = {};
#pragma unroll 1
    for (int ls = 0; ls < 16; ++ls) {
        int dg = ls >> 2, st = ls & 3;
        if (ls < 15) cp_wait<1>(); else cp_wait<0>();
        __syncthreads();
        uint32_t vb = sb + oKB + (uint32_t)(ls & 1) * KBUF;

#pragma unroll
        for (int kt = 0; kt < 8; kt++) {
            uint32_t a[2][4];
#pragma unroll
            for (int mi = 0; mi < 2; mi++) {
                int abase = (mi * 16 + g) * 260 + st * 64 + kt * 8 + t;
                a[mi][0] = Pw[abase];
                a[mi][1] = Pw[abase + 8 * 260];
                a[mi][2] = Pw[abase + 4];
                a[mi][3] = Pw[abase + 8 * 260 + 4];
            }
            uint32_t r0, r1, r2, r3;
            uint32_t addr = vb + (uint32_t)((kt * 16 + (lane & 15)) * 136 +
                                            wid * 16 + ((lane & 16) ? 8 : 0)) * 2;
            ldsm4t(r0, r1, r2, r3, addr);
#pragma unroll
            for (int mi = 0; mi < 2; mi++) {
                mma_f16(cp2[mi][0], a[mi][0], a[mi][1], a[mi][2], a[mi][3], r0, r1);
                mma_f16(cp2[mi][1], a[mi][0], a[mi][1], a[mi][2], a[mi][3], r2, r3);
            }
        }
        __syncthreads();
        if (ls + 2 < 16) stageXN((ls + 2) >> 2, (ls + 2) & 3, ls & 1);

        if (st == 3) {
#pragma unroll
            for (int mi = 0; mi < 2; mi++)
#pragma unroll
                for (int np = 0; np < 2; np++)
#pragma unroll
                    for (int j = 0; j < 4; j++) {
                        int r = mi * 16 + g + ((j >> 1) ? 8 : 0);
                        if (r < P_) {
                            int col = dg * 128 + wid * 16 + np * 8 + t * 2 + (j & 1);
                            g_part[base + (size_t)r * PSTR + 2 + col] = cp2[mi][np][j];
                        }
                        cp2[mi][np][j] = 0.f;
                    }
        }
    }
    if (tid < P_) {
        g_part[base + (size_t)tid * PSTR]     = Ms[tid];
        g_part[base + (size_t)tid * PSTR + 1] = Ls[tid];
    }
}

// ---------------- 5. merge chunk partials -> U ----------------
__global__ __launch_bounds__(512) void merge_kernel() {
    int p = blockIdx.x, h = blockIdx.y, b = blockIdx.z;
    int d = threadIdx.x;
    float M = -3.4e38f;
    for (int c = 0; c < NC_; c++) {
        const float* pp = g_part + (((size_t)(b * H_ + h) * NC_ + c) * P_ + p) * PSTR;
        M = fmaxf(M, pp[0]);
    }
    float L = 0.f, val = 0.f;
    for (int c = 0; c < NC_; c++) {
        const float* pp = g_part + (((size_t)(b * H_ + h) * NC_ + c) * P_ + p) * PSTR;
        float wgt = expf(pp[0] - M);
        L   += pp[1] * wgt;
        val += pp[2 + d] * wgt;
    }
    float out = (L > 0.f) ? val / L : 0.f;
    g_U[(((size_t)b * H_ + h) * P_ + p) * D_ + d] = out;
}

// ---------------- 5b. project: proto_tokens = U @ Wv_h^T ----------------
__global__ __launch_bounds__(512) void proj_kernel() {
    __shared__ float Us[H_ * D_];
    int p = blockIdx.x, b = blockIdx.y, tid = threadIdx.x;
    for (int i = tid; i < H_ * D_; i += 512) {
        int h = i >> 9, k = i & 511;
        Us[i] = g_U[(((size_t)b * H_ + h) * P_ + p) * D_ + k];
    }
    __syncthreads();
    int h = tid >> 7, dd = tid & 127;
    const __half* wr = g_Wh + (size_t)D_ * D_ + (size_t)(h * HD_ + dd) * D_;  // Wv row
    const float* u = Us + h * D_;
    float s = 0.f;
#pragma unroll 8
    for (int k = 0; k < D_; k += 8) {
        uint4 r = *(const uint4*)(wr + k);
        float w[8], dmy = 0.f;
        h8_unpack(r, w, dmy);
        s += w[0] * u[k]     + w[1] * u[k + 1] + w[2] * u[k + 2] + w[3] * u[k + 3]
           + w[4] * u[k + 4] + w[5] * u[k + 5] + w[6] * u[k + 6] + w[7] * u[k + 7];
    }
    g_pt[(b * P_ + p) * D_ + h * HD_ + dd] = s;
}

// ---------------- 6. topk ----------------
__global__ __launch_bounds__(256) void topk_kernel() {
    int b = blockIdx.x, tid = threadIdx.x, w = tid >> 5, lane = tid & 31;
    __shared__ float ss[P_];
    __shared__ int idxs[TOPK_];
#pragma unroll 1
    for (int rr = 0; rr < 3; rr++) {
        int p = w + rr * 8;
        const float* pr = g_pt + (b * P_ + p) * D_;
        float sq = 0.f;
#pragma unroll
        for (int j = 0; j < 16; j++) { float tv = pr[lane + 32 * j]; sq += tv * tv; }
#pragma unroll
        for (int o = 16; o > 0; o >>= 1) sq += __shfl_xor_sync(0xffffffffu, sq, o);
        if (lane == 0) ss[p] = sq;
    }
    __syncthreads();
    if (tid == 0) {
        unsigned used = 0;
        for (int i = 0; i < TOPK_; i++) {
            int best = -1; float bv = -3.4e38f;
            for (int p = 0; p < P_; p++)
                if (!((used >> p) & 1) && ss[p] > bv) { bv = ss[p]; best = p; }
            used |= 1u << best;
            idxs[i] = best;
        }
    }
    __syncthreads();
    for (int d = tid; d < D_; d += 256) {
        float s = 0.f;
        for (int i = 0; i < TOPK_; i++) s += g_pt[(b * P_ + idxs[i]) * D_ + d];
        g_z[b * D_ + d] = s * (1.f / TOPK_);
    }
}

// ---------------- 7. MLP ----------------
__global__ __launch_bounds__(128) void mlp_kernel(int in_sel, const float* __restrict__ W,
                                                  const float* __restrict__ bias,
                                                  float* __restrict__ out_ext, int act) {
    __shared__ float zs[D_];
    int b = blockIdx.y, tid = threadIdx.x;
    int n = blockIdx.x * 128 + tid;
    const float* in = in_sel ? g_hid : g_z;
    for (int i = tid; i < D_; i += 128) zs[i] = in[b * D_ + i];
    __syncthreads();
    const float* wr = W + (size_t)n * D_;
    float s = bias[n];
    for (int k = 0; k < D_; k += 4) {
        float4 w4 = *(const float4*)&wr[k];
        s += w4.x * zs[k] + w4.y * zs[k + 1] + w4.z * zs[k + 2] + w4.w * zs[k + 3];
    }
    if (act) s = s / (1.f + expf(-s));
    float* out = out_ext ? out_ext : g_hid;
    out[b * D_ + n] = s;
}

// ---------------- launch ----------------
extern "C" void kernel_launch(void* const* d_in, const int* in_sizes, int n_in,
                              void* d_out, int out_size) {
    (void)in_sizes; (void)n_in; (void)out_size;
    const float* x     = (const float*)d_in[0];
    const float* proto = (const float*)d_in[1];
    const float* ln_g  = (const float*)d_in[2];
    const float* ln_b  = (const float*)d_in[3];
    const float* Wq    = (const float*)d_in[4];
    const float* Wk    = (const float*)d_in[5];
    const float* Wv    = (const float*)d_in[6];
    const float* W1    = (const float*)d_in[7];
    const float* b1    = (const float*)d_in[8];
    const float* W2    = (const float*)d_in[9];
    const float* b2    = (const float*)d_in[10];
    float* out = (float*)d_out;

    cudaFuncSetAttribute(gemm_ks, cudaFuncAttributeMaxDynamicSharedMemorySize, GEMM_SMEM);
    cudaFuncSetAttribute(att_mma, cudaFuncAttributeMaxDynamicSharedMemorySize, ATT_SMEM);

    ln_kernel<<<(B_ * T_) / 8, 256>>>(x, ln_g, ln_b);
    round_w<<<(D_ * D_) / 256, 256>>>(Wk, Wv);
    qh_kernel<<<dim3(P_, H_), 512>>>(proto, Wq);
    gemm_ks<<<dim3(H_, 512), 256, GEMM_SMEM>>>();
    att_mma<<<dim3(H_, NC_, B_), 256, ATT_SMEM>>>();
    merge_kernel<<<dim3(P_, H_, B_), 512>>>();
    proj_kernel<<<dim3(P_, B_), 512>>>();
    topk_kernel<<<B_, 256>>>();
    mlp_kernel<<<dim3(4, B_), 128>>>(0, W1, b1, nullptr, 1);
    mlp_kernel<<<dim3(4, B_), 128>>>(1, W2, b2, out, 0);
}

// round 17
// speedup vs baseline: 1.2349x; 1.0594x over previous
#include <cuda_runtime.h>
#include <cuda_fp16.h>
#include <cstdint>
#include <cstddef>

#define B_    8
#define T_    8192
#define D_    512
#define H_    4
#define P_    24
#define HD_   128
#define TOPK_ 12
#define NC_   16
#define CHUNK_ 512
#define PSTR  514   // per-proto partial stride: m, l, U[512]

// ---------------- scratch (static device globals; no allocation) ----------------
__device__ __align__(16) __half g_xh[(size_t)B_ * T_ * D_];   // xn (fp16)
__device__ __align__(16) __half g_Wh[2 * D_ * D_];            // Wk, Wv (fp16)
__device__ __align__(16) __half g_S [(size_t)B_ * H_ * P_ * T_];  // scores (fp16)
__device__ float g_Qh[H_ * P_ * HD_];
__device__ float g_part[(size_t)B_ * H_ * NC_ * P_ * PSTR];
__device__ float g_U [(size_t)B_ * H_ * P_ * D_];
__device__ float g_pt[B_ * P_ * D_];
__device__ float g_z [B_ * D_];
__device__ float g_hid[B_ * D_];

// ---------------- helpers ----------------
__device__ __forceinline__ uint32_t smem_u32(const void* p) {
    uint32_t a;
    asm("{ .reg .u64 t; cvta.to.shared.u64 t, %1; cvt.u32.u64 %0, t; }" : "=r"(a) : "l"(p));
    return a;
}
__device__ __forceinline__ void cp16(uint32_t s, const void* g) {
    asm volatile("cp.async.cg.shared.global [%0], [%1], 16;" :: "r"(s), "l"(g) : "memory");
}
__device__ __forceinline__ void cp_commit() {
    asm volatile("cp.async.commit_group;" ::: "memory");
}
template <int N> __device__ __forceinline__ void cp_wait() {
    asm volatile("cp.async.wait_group %0;" :: "n"(N) : "memory");
}
__device__ __forceinline__ void ldsm4(uint32_t& r0, uint32_t& r1, uint32_t& r2, uint32_t& r3,
                                      uint32_t addr) {
    asm volatile("ldmatrix.sync.aligned.m8n8.x4.shared.b16 {%0,%1,%2,%3}, [%4];"
                 : "=r"(r0), "=r"(r1), "=r"(r2), "=r"(r3) : "r"(addr));
}
__device__ __forceinline__ void ldsm4t(uint32_t& r0, uint32_t& r1, uint32_t& r2, uint32_t& r3,
                                       uint32_t addr) {
    asm volatile("ldmatrix.sync.aligned.m8n8.x4.trans.shared.b16 {%0,%1,%2,%3}, [%4];"
                 : "=r"(r0), "=r"(r1), "=r"(r2), "=r"(r3) : "r"(addr));
}
__device__ __forceinline__ void mma_f16(float* c,
                                        uint32_t a0, uint32_t a1, uint32_t a2, uint32_t a3,
                                        uint32_t b0, uint32_t b1) {
    asm volatile("mma.sync.aligned.m16n8k16.row.col.f32.f16.f16.f32 "
                 "{%0,%1,%2,%3}, {%4,%5,%6,%7}, {%8,%9}, {%0,%1,%2,%3};"
                 : "+f"(c[0]), "+f"(c[1]), "+f"(c[2]), "+f"(c[3])
                 : "r"(a0), "r"(a1), "r"(a2), "r"(a3), "r"(b0), "r"(b1));
}
__device__ __forceinline__ void h8_unpack(uint4 r, float* o, float& nn) {
    float2 f;
    f = __half22float2(*(__half2*)&r.x); o[0] = f.x; o[1] = f.y; nn += f.x * f.x + f.y * f.y;
    f = __half22float2(*(__half2*)&r.y); o[2] = f.x; o[3] = f.y; nn += f.x * f.x + f.y * f.y;
    f = __half22float2(*(__half2*)&r.z); o[4] = f.x; o[5] = f.y; nn += f.x * f.x + f.y * f.y;
    f = __half22float2(*(__half2*)&r.w); o[6] = f.x; o[7] = f.y; nn += f.x * f.x + f.y * f.y;
}

// ---------------- 1. LayerNorm -> fp16 ----------------
__global__ __launch_bounds__(256) void ln_kernel(const float* __restrict__ x,
                                                 const float* __restrict__ gw,
                                                 const float* __restrict__ bw) {
    int lane = threadIdx.x & 31;
    size_t row = (size_t)blockIdx.x * 8 + (threadIdx.x >> 5);
    const float* xr = x + row * D_;
    float4 v[4];
    float s = 0.f, sq = 0.f;
#pragma unroll
    for (int j = 0; j < 4; j++) {
        v[j] = *(const float4*)&xr[lane * 4 + j * 128];
        s  += v[j].x + v[j].y + v[j].z + v[j].w;
        sq += v[j].x * v[j].x + v[j].y * v[j].y + v[j].z * v[j].z + v[j].w * v[j].w;
    }
#pragma unroll
    for (int o = 16; o > 0; o >>= 1) {
        s  += __shfl_xor_sync(0xffffffffu, s,  o);
        sq += __shfl_xor_sync(0xffffffffu, sq, o);
    }
    float mu   = s * (1.f / 512.f);
    float var  = sq * (1.f / 512.f) - mu * mu;
    float rstd = rsqrtf(var + 1e-5f);
#pragma unroll
    for (int j = 0; j < 4; j++) {
        int c = lane * 4 + j * 128;
        float4 gv = *(const float4*)&gw[c];
        float4 bv = *(const float4*)&bw[c];
        __half h[4];
        h[0] = __float2half_rn((v[j].x - mu) * rstd * gv.x + bv.x);
        h[1] = __float2half_rn((v[j].y - mu) * rstd * gv.y + bv.y);
        h[2] = __float2half_rn((v[j].z - mu) * rstd * gv.z + bv.z);
        h[3] = __float2half_rn((v[j].w - mu) * rstd * gv.w + bv.w);
        *(uint2*)&g_xh[row * D_ + c] = *(uint2*)h;
    }
}

// ---------------- 1b. W matrices -> fp16 ----------------
__global__ __launch_bounds__(256) void round_w(const float* __restrict__ Wk,
                                               const float* __restrict__ Wv) {
    int i = blockIdx.x * 256 + threadIdx.x;
    g_Wh[i]           = __float2half_rn(Wk[i]);
    g_Wh[D_ * D_ + i] = __float2half_rn(Wv[i]);
}

// ---------------- 3. Qh: grid (P, H), 512 threads ----------------
__global__ __launch_bounds__(512) void qh_kernel(const float* __restrict__ proto,
                                                 const float* __restrict__ Wq) {
    __shared__ float pr[D_];
    __shared__ float qp[HD_];
    __shared__ float sinv;
    int p = blockIdx.x, h = blockIdx.y, tid = threadIdx.x;
    pr[tid] = proto[p * D_ + tid];
    __syncthreads();
    int nl = tid >> 2, part = tid & 3;
    const float* wr = Wq + (size_t)(h * HD_ + nl) * D_ + part * 128;
    const float* pp = pr + part * 128;
    float a = 0.f;
#pragma unroll 8
    for (int k = 0; k < 128; k += 4) {
        float4 w4 = *(const float4*)&wr[k];
        a += w4.x * pp[k] + w4.y * pp[k + 1] + w4.z * pp[k + 2] + w4.w * pp[k + 3];
    }
    a += __shfl_xor_sync(0xffffffffu, a, 1);
    a += __shfl_xor_sync(0xffffffffu, a, 2);
    if (part == 0) qp[nl] = a;
    __syncthreads();
    if (tid < 32) {
        float sq = 0.f;
#pragma unroll
        for (int j = 0; j < 4; j++) { float tv = qp[tid + 32 * j]; sq += tv * tv; }
#pragma unroll
        for (int o = 16; o > 0; o >>= 1) sq += __shfl_xor_sync(0xffffffffu, sq, o);
        if (tid == 0) sinv = 1.f / fmaxf(sqrtf(sq), 1e-12f);
    }
    __syncthreads();
    if (tid < HD_) g_Qh[(h * P_ + p) * HD_ + tid] = qp[tid] * sinv;
}

// ---------------- 2. fused GEMM + scores (unchanged from R16) ----------------
#define ROWB 80
#define TILE_B (128 * ROWB)
#define STAGE_B (2 * TILE_B)
#define GEMM_SMEM (3 * STAGE_B)    // 61440 B
#define eKT 0
#define eQ  34816
#define eNm 43520

__global__ __launch_bounds__(256, 2) void gemm_ks() {
    extern __shared__ __align__(16) char smc[];
    const uint32_t sb = smem_u32(smc);

    const int tid = threadIdx.x;
    const int wid = tid >> 5, lane = tid & 31;
    const int h  = blockIdx.x;
    const int n0 = h * 128;
    const size_t m0 = (size_t)blockIdx.y * 128;
    const int b    = blockIdx.y >> 6;
    const int tok0 = (blockIdx.y & 63) * 128;

    const __half* A_g = g_xh;
    const __half* B_g = g_Wh;           // Wk

    const int lrow = tid >> 1;
    const int lch  = tid & 1;
    const size_t gA = (m0 + lrow) * D_ + lch * 16;
    const size_t gB = (size_t)(n0 + lrow) * D_ + lch * 16;
    const uint32_t sRow = (uint32_t)lrow * ROWB + lch * 32;

    const int wm = (wid >> 2) * 64;
    const int wn = (wid & 3) * 32;
    const int g  = lane >> 2;
    const int t  = lane & 3;

    uint32_t aRow[4], bRow[2];
#pragma unroll
    for (int mi = 0; mi < 4; mi++)
        aRow[mi] = (uint32_t)(wm + mi * 16 + (lane & 15)) * ROWB + ((lane & 16) ? 16 : 0);
#pragma unroll
    for (int np = 0; np < 2; np++)
        bRow[np] = (uint32_t)(wn + np * 16 + ((lane & 16) ? 8 : 0) + (lane & 7)) * ROWB
                   + ((lane & 8) ? 16 : 0);

    float c[4][4][4];
#pragma unroll
    for (int mi = 0; mi < 4; mi++)
#pragma unroll
        for (int ni = 0; ni < 4; ni++)
#pragma unroll
            for (int j = 0; j < 4; j++) c[mi][ni][j] = 0.f;

    auto stage = [&](int st, int kt) {
        uint32_t bbA = sb + (uint32_t)st * STAGE_B;
        uint32_t bbB = bbA + TILE_B;
        int ke = kt * 32;
        cp16(bbA + sRow,      A_g + gA + ke);
        cp16(bbA + sRow + 16, A_g + gA + ke + 8);
        cp16(bbB + sRow,      B_g + gB + ke);
        cp16(bbB + sRow + 16, B_g + gB + ke + 8);
        cp_commit();
    };

    stage(0, 0);
    stage(1, 1);

#pragma unroll 1
    for (int kt = 0; kt < 16; ++kt) {
        if (kt < 15) cp_wait<1>(); else cp_wait<0>();
        __syncthreads();
        if (kt + 2 < 16) stage((kt + 2) % 3, kt + 2);

        const uint32_t bbA = sb + (uint32_t)(kt % 3) * STAGE_B;
        const uint32_t bbB = bbA + TILE_B;

#pragma unroll
        for (int ks = 0; ks < 2; ks++) {
            const uint32_t ko = ks * 32;
            uint32_t a[4][4], bq[2][4];
#pragma unroll
            for (int mi = 0; mi < 4; mi++)
                ldsm4(a[mi][0], a[mi][1], a[mi][2], a[mi][3], bbA + aRow[mi] + ko);
#pragma unroll
            for (int np = 0; np < 2; np++)
                ldsm4(bq[np][0], bq[np][1], bq[np][2], bq[np][3], bbB + bRow[np] + ko);
#pragma unroll
            for (int mi = 0; mi < 4; mi++)
#pragma unroll
                for (int np = 0; np < 2; np++) {
                    mma_f16(c[mi][np * 2],     a[mi][0], a[mi][1], a[mi][2], a[mi][3],
                            bq[np][0], bq[np][1]);
                    mma_f16(c[mi][np * 2 + 1], a[mi][0], a[mi][1], a[mi][2], a[mi][3],
                            bq[np][2], bq[np][3]);
                }
        }
    }
    __syncthreads();

    __half* Kt = (__half*)(smc + eKT);
    __half* Qs = (__half*)(smc + eQ);
    float*  Nm = (float*)(smc + eNm);
#pragma unroll
    for (int mi = 0; mi < 4; mi++)
#pragma unroll
        for (int ni = 0; ni < 4; ni++) {
            int r0 = wm + mi * 16 + g;
            int col = wn + ni * 8 + t * 2;
            *(__half2*)&Kt[r0 * 136 + col]       = __floats2half2_rn(c[mi][ni][0], c[mi][ni][1]);
            *(__half2*)&Kt[(r0 + 8) * 136 + col] = __floats2half2_rn(c[mi][ni][2], c[mi][ni][3]);
        }
    for (int i = tid; i < 32 * 128; i += 256) {
        int p = i >> 7, d = i & 127;
        float v = (p < P_) ? g_Qh[(h * P_ + p) * HD_ + d] : 0.f;
        Qs[p * 136 + d] = __float2half_rn(v);
    }
    __syncthreads();

    {
        int tok = tid >> 1, hf = tid & 1;
        const uint4* kp = (const uint4*)(Kt + tok * 136 + hf * 64);
        float nn = 0.f, tmp[8];
#pragma unroll
        for (int i = 0; i < 8; i++) h8_unpack(kp[i], tmp, nn);
        nn += __shfl_xor_sync(0xffffffffu, nn, 1);
        if (hf == 0) Nm[tok] = nn;
    }
    __syncthreads();

    const uint32_t* Qw = (const uint32_t*)Qs;
    const uint32_t* Kw = (const uint32_t*)Kt;
    float c2[2][2][4] = {};
#pragma unroll
    for (int kt = 0; kt < 8; kt++) {
        uint32_t a[2][4];
#pragma unroll
        for (int mi = 0; mi < 2; mi++) {
            int base = (mi * 16 + g) * 68 + kt * 8 + t;
            a[mi][0] = Qw[base];
            a[mi][1] = Qw[base + 8 * 68];
            a[mi][2] = Qw[base + 4];
            a[mi][3] = Qw[base + 8 * 68 + 4];
        }
#pragma unroll
        for (int np = 0; np < 2; np++) {
            int tok = wid * 16 + np * 8 + g;
            int base = tok * 68 + kt * 8 + t;
            uint32_t b0 = Kw[base], b1 = Kw[base + 4];
#pragma unroll
            for (int mi = 0; mi < 2; mi++)
                mma_f16(c2[mi][np], a[mi][0], a[mi][1], a[mi][2], a[mi][3], b0, b1);
        }
    }
#pragma unroll
    for (int np = 0; np < 2; np++) {
        int tc = wid * 16 + np * 8 + t * 2;
        float inv0 = 1.f / (fmaxf(sqrtf(Nm[tc]),     1e-12f) * 0.07f);
        float inv1 = 1.f / (fmaxf(sqrtf(Nm[tc + 1]), 1e-12f) * 0.07f);
#pragma unroll
        for (int mi = 0; mi < 2; mi++) {
            int r0 = mi * 16 + g;
            if (r0 < P_)
                *(__half2*)&g_S[((size_t)(b * H_ + h) * P_ + r0) * T_ + tok0 + tc] =
                    __floats2half2_rn(c2[mi][np][0] * inv0, c2[mi][np][1] * inv1);
            if (r0 + 8 < P_)
                *(__half2*)&g_S[((size_t)(b * H_ + h) * P_ + r0 + 8) * T_ + tok0 + tc] =
                    __floats2half2_rn(c2[mi][np][2] * inv0, c2[mi][np][3] * inv1);
        }
    }
}

// ---------------- 4. attention: ALL HEADS per block (96-row PV) ----------------
// grid (NC, B), 256 threads. smem 170240 B -> 1 CTA/SM, 128 blocks ~ 1 wave.
#define oSP2  0                       // 96 x 520 halves = 99840 B
#define oKB2  99840                   // 2 x 34816
#define KBUF2 34816
#define oMs2  169472                  // 96 floats
#define oLs2  169856                  // 96 floats
#define ATT_SMEM 170240

__global__ __launch_bounds__(256, 1) void att_mma() {
    extern __shared__ __align__(16) char smc[];
    const uint32_t sb = smem_u32(smc);
    __half* SP = (__half*)(smc + oSP2);    // 96 rows (h*24+p) x 520
    float*  Ms = (float*)(smc + oMs2);
    float*  Ls = (float*)(smc + oLs2);
    const uint32_t* Pw = (const uint32_t*)SP;

    const int tid = threadIdx.x;
    const int wid = tid >> 5, lane = tid & 31;
    const int g = lane >> 2, t = lane & 3;
    const int cz = blockIdx.x, b = blockIdx.y;
    const size_t tokbase = (size_t)(b * T_ + cz * CHUNK_);

    auto stageXN = [&](int dg, int st, int bf) {
        uint32_t bb = sb + oKB2 + (uint32_t)bf * KBUF2;
#pragma unroll
        for (int j = 0; j < 8; j++) {
            int lin = tid + 256 * j;
            int tok = lin >> 4, ch = lin & 15;
            cp16(bb + (uint32_t)(tok * 136 + ch * 8) * 2,
                 g_xh + (tokbase + st * 128 + tok) * D_ + dg * 128 + ch * 8);
        }
        cp_commit();
    };

    // stage scores for all 4 heads: 96 rows x 512 tokens (row = h*24+p)
    {
        const __half* src0 = g_S + (size_t)b * H_ * P_ * T_ + cz * CHUNK_;
#pragma unroll
        for (int j = 0; j < 24; j++) {
            int lin = tid + 256 * j;          // 0..6143
            int row = lin >> 6, ch = lin & 63;
            cp16(sb + oSP2 + (uint32_t)(row * 520 + ch * 8) * 2,
                 src0 + (size_t)row * T_ + ch * 8);    // g_S rows are (b, h, p) contiguous
        }
        cp_commit();
    }
    stageXN(0, 0, 0);
    stageXN(0, 1, 1);

    cp_wait<2>();        // scores landed
    __syncthreads();

    // ================= softmax in place on SP (96 rows) =================
#pragma unroll 1
    for (int rr = 0; rr < 12; ++rr) {
        int p = wid + rr * 8;
        float vals[16];
        float m = -3.4e38f;
#pragma unroll
        for (int j = 0; j < 16; j++) {
            vals[j] = __half2float(SP[p * 520 + lane + 32 * j]);
            m = fmaxf(m, vals[j]);
        }
#pragma unroll
        for (int o = 16; o > 0; o >>= 1) m = fmaxf(m, __shfl_xor_sync(0xffffffffu, m, o));
        float s = 0.f;
#pragma unroll
        for (int j = 0; j < 16; j++) {
            float e = expf(vals[j] - m);
            SP[p * 520 + lane + 32 * j] = __float2half_rn(e);
            s += e;
        }
#pragma unroll
        for (int o = 16; o > 0; o >>= 1) s += __shfl_xor_sync(0xffffffffu, s, o);
        if (lane == 0) { Ms[p] = m; Ls[p] = s; }
    }

    // ================= PV: U = P @ xn (96 rows = 6 m16 groups) =================
    float cp2[6][2][4] = {};
#pragma unroll 1
    for (int ls = 0; ls < 16; ++ls) {
        int dg = ls >> 2, st = ls & 3;
        if (ls < 15) cp_wait<1>(); else cp_wait<0>();
        __syncthreads();
        uint32_t vb = sb + oKB2 + (uint32_t)(ls & 1) * KBUF2;

#pragma unroll
        for (int kt = 0; kt < 8; kt++) {
            uint32_t a[6][4];
#pragma unroll
            for (int mi = 0; mi < 6; mi++) {
                int abase = (mi * 16 + g) * 260 + st * 64 + kt * 8 + t;
                a[mi][0] = Pw[abase];
                a[mi][1] = Pw[abase + 8 * 260];
                a[mi][2] = Pw[abase + 4];
                a[mi][3] = Pw[abase + 8 * 260 + 4];
            }
            uint32_t r0, r1, r2, r3;
            uint32_t addr = vb + (uint32_t)((kt * 16 + (lane & 15)) * 136 +
                                            wid * 16 + ((lane & 16) ? 8 : 0)) * 2;
            ldsm4t(r0, r1, r2, r3, addr);
#pragma unroll
            for (int mi = 0; mi < 6; mi++) {
                mma_f16(cp2[mi][0], a[mi][0], a[mi][1], a[mi][2], a[mi][3], r0, r1);
                mma_f16(cp2[mi][1], a[mi][0], a[mi][1], a[mi][2], a[mi][3], r2, r3);
            }
        }
        __syncthreads();
        if (ls + 2 < 16) stageXN((ls + 2) >> 2, (ls + 2) & 3, ls & 1);

        if (st == 3) {
#pragma unroll
            for (int mi = 0; mi < 6; mi++)
#pragma unroll
                for (int np = 0; np < 2; np++)
#pragma unroll
                    for (int j = 0; j < 4; j++) {
                        int r = mi * 16 + g + ((j >> 1) ? 8 : 0);   // 0..95
                        int hh = r / P_, pp = r % P_;
                        int col = dg * 128 + wid * 16 + np * 8 + t * 2 + (j & 1);
                        size_t baseh = (((size_t)(b * H_ + hh) * NC_ + cz) * P_) * PSTR;
                        g_part[baseh + (size_t)pp * PSTR + 2 + col] = cp2[mi][np][j];
                        cp2[mi][np][j] = 0.f;
                    }
        }
    }
    if (tid < 96) {
        int hh = tid / P_, pp = tid % P_;
        size_t baseh = (((size_t)(b * H_ + hh) * NC_ + cz) * P_) * PSTR;
        g_part[baseh + (size_t)pp * PSTR]     = Ms[tid];
        g_part[baseh + (size_t)pp * PSTR + 1] = Ls[tid];
    }
}

// ---------------- 5. merge chunk partials -> U ----------------
__global__ __launch_bounds__(512) void merge_kernel() {
    int p = blockIdx.x, h = blockIdx.y, b = blockIdx.z;
    int d = threadIdx.x;
    float M = -3.4e38f;
    for (int c = 0; c < NC_; c++) {
        const float* pp = g_part + (((size_t)(b * H_ + h) * NC_ + c) * P_ + p) * PSTR;
        M = fmaxf(M, pp[0]);
    }
    float L = 0.f, val = 0.f;
    for (int c = 0; c < NC_; c++) {
        const float* pp = g_part + (((size_t)(b * H_ + h) * NC_ + c) * P_ + p) * PSTR;
        float wgt = expf(pp[0] - M);
        L   += pp[1] * wgt;
        val += pp[2 + d] * wgt;
    }
    float out = (L > 0.f) ? val / L : 0.f;
    g_U[(((size_t)b * H_ + h) * P_ + p) * D_ + d] = out;
}

// ---------------- 5b. project: proto_tokens = U @ Wv_h^T ----------------
__global__ __launch_bounds__(512) void proj_kernel() {
    __shared__ float Us[H_ * D_];
    int p = blockIdx.x, b = blockIdx.y, tid = threadIdx.x;
    for (int i = tid; i < H_ * D_; i += 512) {
        int h = i >> 9, k = i & 511;
        Us[i] = g_U[(((size_t)b * H_ + h) * P_ + p) * D_ + k];
    }
    __syncthreads();
    int h = tid >> 7, dd = tid & 127;
    const __half* wr = g_Wh + (size_t)D_ * D_ + (size_t)(h * HD_ + dd) * D_;  // Wv row
    const float* u = Us + h * D_;
    float s = 0.f;
#pragma unroll 8
    for (int k = 0; k < D_; k += 8) {
        uint4 r = *(const uint4*)(wr + k);
        float w[8], dmy = 0.f;
        h8_unpack(r, w, dmy);
        s += w[0] * u[k]     + w[1] * u[k + 1] + w[2] * u[k + 2] + w[3] * u[k + 3]
           + w[4] * u[k + 4] + w[5] * u[k + 5] + w[6] * u[k + 6] + w[7] * u[k + 7];
    }
    g_pt[(b * P_ + p) * D_ + h * HD_ + dd] = s;
}

// ---------------- 6. topk ----------------
__global__ __launch_bounds__(256) void topk_kernel() {
    int b = blockIdx.x, tid = threadIdx.x, w = tid >> 5, lane = tid & 31;
    __shared__ float ss[P_];
    __shared__ int idxs[TOPK_];
#pragma unroll 1
    for (int rr = 0; rr < 3; rr++) {
        int p = w + rr * 8;
        const float* pr = g_pt + (b * P_ + p) * D_;
        float sq = 0.f;
#pragma unroll
        for (int j = 0; j < 16; j++) { float tv = pr[lane + 32 * j]; sq += tv * tv; }
#pragma unroll
        for (int o = 16; o > 0; o >>= 1) sq += __shfl_xor_sync(0xffffffffu, sq, o);
        if (lane == 0) ss[p] = sq;
    }
    __syncthreads();
    if (tid == 0) {
        unsigned used = 0;
        for (int i = 0; i < TOPK_; i++) {
            int best = -1; float bv = -3.4e38f;
            for (int p = 0; p < P_; p++)
                if (!((used >> p) & 1) && ss[p] > bv) { bv = ss[p]; best = p; }
            used |= 1u << best;
            idxs[i] = best;
        }
    }
    __syncthreads();
    for (int d = tid; d < D_; d += 256) {
        float s = 0.f;
        for (int i = 0; i < TOPK_; i++) s += g_pt[(b * P_ + idxs[i]) * D_ + d];
        g_z[b * D_ + d] = s * (1.f / TOPK_);
    }
}

// ---------------- 7. MLP ----------------
__global__ __launch_bounds__(128) void mlp_kernel(int in_sel, const float* __restrict__ W,
                                                  const float* __restrict__ bias,
                                                  float* __restrict__ out_ext, int act) {
    __shared__ float zs[D_];
    int b = blockIdx.y, tid = threadIdx.x;
    int n = blockIdx.x * 128 + tid;
    const float* in = in_sel ? g_hid : g_z;
    for (int i = tid; i < D_; i += 128) zs[i] = in[b * D_ + i];
    __syncthreads();
    const float* wr = W + (size_t)n * D_;
    float s = bias[n];
    for (int k = 0; k < D_; k += 4) {
        float4 w4 = *(const float4*)&wr[k];
        s += w4.x * zs[k] + w4.y * zs[k + 1] + w4.z * zs[k + 2] + w4.w * zs[k + 3];
    }
    if (act) s = s / (1.f + expf(-s));
    float* out = out_ext ? out_ext : g_hid;
    out[b * D_ + n] = s;
}

// ---------------- launch ----------------
extern "C" void kernel_launch(void* const* d_in, const int* in_sizes, int n_in,
                              void* d_out, int out_size) {
    (void)in_sizes; (void)n_in; (void)out_size;
    const float* x     = (const float*)d_in[0];
    const float* proto = (const float*)d_in[1];
    const float* ln_g  = (const float*)d_in[2];
    const float* ln_b  = (const float*)d_in[3];
    const float* Wq    = (const float*)d_in[4];
    const float* Wk    = (const float*)d_in[5];
    const float* Wv    = (const float*)d_in[6];
    const float* W1    = (const float*)d_in[7];
    const float* b1    = (const float*)d_in[8];
    const float* W2    = (const float*)d_in[9];
    const float* b2    = (const float*)d_in[10];
    float* out = (float*)d_out;

    cudaFuncSetAttribute(gemm_ks, cudaFuncAttributeMaxDynamicSharedMemorySize, GEMM_SMEM);
    cudaFuncSetAttribute(att_mma, cudaFuncAttributeMaxDynamicSharedMemorySize, ATT_SMEM);

    ln_kernel<<<(B_ * T_) / 8, 256>>>(x, ln_g, ln_b);
    round_w<<<(D_ * D_) / 256, 256>>>(Wk, Wv);
    qh_kernel<<<dim3(P_, H_), 512>>>(proto, Wq);
    gemm_ks<<<dim3(H_, 512), 256, GEMM_SMEM>>>();
    att_mma<<<dim3(NC_, B_), 256, ATT_SMEM>>>();
    merge_kernel<<<dim3(P_, H_, B_), 512>>>();
    proj_kernel<<<dim3(P_, B_), 512>>>();
    topk_kernel<<<B_, 256>>>();
    mlp_kernel<<<dim3(4, B_), 128>>>(0, W1, b1, nullptr, 1);
    mlp_kernel<<<dim3(4, B_), 128>>>(1, W2, b2, out, 0);
}